// round 2
// baseline (speedup 1.0000x reference)
#include <cuda_runtime.h>
#include <math.h>

typedef unsigned long long u64;

#define B_  32
#define TQ_ 1024
#define TK_ 1024
#define D_  64

// 134 MB scores scratch + per-row softmax stats (static device bss; no runtime alloc)
static __device__ float g_S[(size_t)B_ * TQ_ * TK_];
static __device__ float g_mx[B_ * TQ_];
static __device__ float g_inv[B_ * TQ_];

// ---- packed f32x2 helpers (Blackwell 2x fp32 FMA rate) ----------------------
__device__ __forceinline__ u64 pack2(float lo, float hi) {
    u64 d;
    asm("mov.b64 %0,{%1,%2};" : "=l"(d)
        : "r"(__float_as_uint(lo)), "r"(__float_as_uint(hi)));
    return d;
}
__device__ __forceinline__ float2 unpack2(u64 v) {
    unsigned lo, hi;
    asm("mov.b64 {%0,%1},%2;" : "=r"(lo), "=r"(hi) : "l"(v));
    return make_float2(__uint_as_float(lo), __uint_as_float(hi));
}
__device__ __forceinline__ void fma2(u64& d, u64 a, u64 b) {
    asm("fma.rn.f32x2 %0,%1,%2,%0;" : "+l"(d) : "l"(a), "l"(b));
}

// ---------------------------------------------------------------------------
// Kernel A: content scores  S[b,q,k] = sum_d Q[b,q,d] * K[b,k,d]   (unscaled)
// grid (TK/128, TQ/128, B), 256 threads, 128x128 tile, 8x8 microtile, f32x2
// ---------------------------------------------------------------------------
extern "C" __global__ void __launch_bounds__(256)
qk_kernel(const float* __restrict__ Q, const float* __restrict__ K)
{
    const int bz = blockIdx.z;
    const int qt = blockIdx.y * 128;
    const int kt = blockIdx.x * 128;
    const float* Qb = Q + (size_t)bz * TQ_ * D_;
    const float* Kb = K + (size_t)bz * TK_ * D_;
    float* Sb = g_S + (size_t)bz * TQ_ * TK_;

    __shared__ float Qs[32][132];   // [d][m], padded
    __shared__ float Ks[32][132];   // [d][n], padded

    const int tid = threadIdx.x;
    const int ty  = tid >> 4;       // 0..15
    const int tx  = tid & 15;       // 0..15

    u64 acc[8][4];
#pragma unroll
    for (int i = 0; i < 8; i++)
#pragma unroll
        for (int j = 0; j < 4; j++) acc[i][j] = 0ull;

    for (int k0 = 0; k0 < D_; k0 += 32) {
#pragma unroll
        for (int i = 0; i < 4; i++) {
            int idx = tid + i * 256;        // float4 index over 128x32 tile
            int row = idx >> 3;
            int dc  = (idx & 7) * 4;
            float4 v = *(const float4*)(Qb + (size_t)(qt + row) * D_ + k0 + dc);
            Qs[dc + 0][row] = v.x; Qs[dc + 1][row] = v.y;
            Qs[dc + 2][row] = v.z; Qs[dc + 3][row] = v.w;
            float4 w = *(const float4*)(Kb + (size_t)(kt + row) * D_ + k0 + dc);
            Ks[dc + 0][row] = w.x; Ks[dc + 1][row] = w.y;
            Ks[dc + 2][row] = w.z; Ks[dc + 3][row] = w.w;
        }
        __syncthreads();
#pragma unroll 4
        for (int kk = 0; kk < 32; kk++) {
            float4 a0 = *(const float4*)&Qs[kk][ty * 8];
            float4 a1 = *(const float4*)&Qs[kk][ty * 8 + 4];
            ulonglong2 kb0 = *(const ulonglong2*)&Ks[kk][tx * 8];
            ulonglong2 kb1 = *(const ulonglong2*)&Ks[kk][tx * 8 + 4];
            u64 bp0 = kb0.x, bp1 = kb0.y, bp2 = kb1.x, bp3 = kb1.y;
            u64 ap[8];
            ap[0] = pack2(a0.x, a0.x); ap[1] = pack2(a0.y, a0.y);
            ap[2] = pack2(a0.z, a0.z); ap[3] = pack2(a0.w, a0.w);
            ap[4] = pack2(a1.x, a1.x); ap[5] = pack2(a1.y, a1.y);
            ap[6] = pack2(a1.z, a1.z); ap[7] = pack2(a1.w, a1.w);
#pragma unroll
            for (int i = 0; i < 8; i++) {
                fma2(acc[i][0], ap[i], bp0);
                fma2(acc[i][1], ap[i], bp1);
                fma2(acc[i][2], ap[i], bp2);
                fma2(acc[i][3], ap[i], bp3);
            }
        }
        __syncthreads();
    }

#pragma unroll
    for (int i = 0; i < 8; i++) {
        float2 c0 = unpack2(acc[i][0]);
        float2 c1 = unpack2(acc[i][1]);
        float2 c2 = unpack2(acc[i][2]);
        float2 c3 = unpack2(acc[i][3]);
        float* dst = Sb + (size_t)(qt + ty * 8 + i) * TK_ + kt + tx * 8;
        *(float4*)(dst)     = make_float4(c0.x, c0.y, c1.x, c1.y);
        *(float4*)(dst + 4) = make_float4(c2.x, c2.y, c3.x, c3.y);
    }
}

// ---------------------------------------------------------------------------
// Kernel B: S[b,q,k] = mask( (S + sum_d Q[b,q,d]*pos_k[q,k,d]) / 8 )
// grid (TK/128, TQ), 256 threads. pos_k read exactly once. f32x2 dot products.
// thread: kg = tid&7 (k = kg + 8j, j<16), b = tid>>3
// ---------------------------------------------------------------------------
extern "C" __global__ void __launch_bounds__(256, 2)
posk_kernel(const float* __restrict__ Q, const float* __restrict__ PK,
            const int* __restrict__ VL)
{
    const int q  = blockIdx.y;
    const int kt = blockIdx.x * 128;

    __shared__ float Ps[128][68];   // pos_k chunk, natural [k][d], padded
    __shared__ float Qs[B_][D_];    // Q[:,q,:]
    __shared__ int   vls[B_];

    const int tid = threadIdx.x;

    const float* PKq = PK + ((size_t)q * TK_ + kt) * D_;
#pragma unroll
    for (int i = 0; i < 8; i++) {
        int idx = tid + i * 256;        // 2048 float4 over 128x64
        int k  = idx >> 4;
        int dc = (idx & 15) * 4;
        *(float4*)&Ps[k][dc] = *(const float4*)(PKq + (size_t)k * D_ + dc);
    }
#pragma unroll
    for (int i = 0; i < 2; i++) {
        int idx = tid + i * 256;        // 512 float4 over 32x64
        int bb = idx >> 4;
        int dc = (idx & 15) * 4;
        *(float4*)&Qs[bb][dc] = *(const float4*)(Q + ((size_t)bb * TQ_ + q) * D_ + dc);
    }
    if (tid < B_) vls[tid] = VL[tid];
    __syncthreads();

    const int kg = tid & 7;
    const int b  = tid >> 3;

    u64 qp[32];                     // Q row as 32 packed pairs
#pragma unroll
    for (int i = 0; i < 16; i++) {
        ulonglong2 t = *(const ulonglong2*)&Qs[b][i * 4];
        qp[i * 2 + 0] = t.x;
        qp[i * 2 + 1] = t.y;
    }

    float acc[16];
#pragma unroll 2
    for (int j = 0; j < 16; j++) {
        const int k = kg + j * 8;
        u64 s0 = 0ull, s1 = 0ull, s2 = 0ull, s3 = 0ull;
#pragma unroll
        for (int dc = 0; dc < 64; dc += 16) {
            const int t = dc >> 1;
            ulonglong2 p0 = *(const ulonglong2*)&Ps[k][dc];
            ulonglong2 p1 = *(const ulonglong2*)&Ps[k][dc + 4];
            ulonglong2 p2 = *(const ulonglong2*)&Ps[k][dc + 8];
            ulonglong2 p3 = *(const ulonglong2*)&Ps[k][dc + 12];
            fma2(s0, qp[t + 0], p0.x);
            fma2(s1, qp[t + 1], p0.y);
            fma2(s2, qp[t + 2], p1.x);
            fma2(s3, qp[t + 3], p1.y);
            fma2(s0, qp[t + 4], p2.x);
            fma2(s1, qp[t + 5], p2.y);
            fma2(s2, qp[t + 6], p3.x);
            fma2(s3, qp[t + 7], p3.y);
        }
        float2 r0 = unpack2(s0), r1 = unpack2(s1);
        float2 r2 = unpack2(s2), r3 = unpack2(s3);
        acc[j] = ((r0.x + r0.y) + (r1.x + r1.y)) + ((r2.x + r2.y) + (r3.x + r3.y));
    }

    const int vl = vls[b];
    float* Srow = g_S + ((size_t)b * TQ_ + q) * TK_ + kt;
#pragma unroll
    for (int j = 0; j < 16; j++) {
        int k = kg + j * 8;
        float s = Srow[k];
        Srow[k] = (kt + k < vl) ? (s + acc[j]) * 0.125f : -1e6f;
    }
}

// ---------------------------------------------------------------------------
// Kernel C: row softmax STATS over k (1024): g_mx = rowmax, g_inv = 1/sum(exp)
// grid (TQ, B), 256 threads, 4 elem/thr. S itself is NOT rewritten.
// ---------------------------------------------------------------------------
extern "C" __global__ void __launch_bounds__(256)
stats_kernel()
{
    const int q = blockIdx.x;
    const int b = blockIdx.y;
    const float* row = g_S + ((size_t)b * TQ_ + q) * TK_;
    const int tid = threadIdx.x;

    float4 v = *(const float4*)&row[tid * 4];
    float m = fmaxf(fmaxf(v.x, v.y), fmaxf(v.z, v.w));
#pragma unroll
    for (int o = 16; o > 0; o >>= 1) m = fmaxf(m, __shfl_xor_sync(0xffffffffu, m, o));

    __shared__ float red[8];
    if ((tid & 31) == 0) red[tid >> 5] = m;
    __syncthreads();
    float M = red[0];
#pragma unroll
    for (int i = 1; i < 8; i++) M = fmaxf(M, red[i]);

    float s = (__expf(v.x - M) + __expf(v.y - M)) +
              (__expf(v.z - M) + __expf(v.w - M));
#pragma unroll
    for (int o = 16; o > 0; o >>= 1) s += __shfl_xor_sync(0xffffffffu, s, o);
    __syncthreads();
    if ((tid & 31) == 0) red[tid >> 5] = s;
    __syncthreads();
    if (tid == 0) {
        float tot = 0.f;
#pragma unroll
        for (int i = 0; i < 8; i++) tot += red[i];
        g_mx[b * TQ_ + q]  = M;
        g_inv[b * TQ_ + q] = 1.0f / tot;
    }
}

// ---------------------------------------------------------------------------
// Kernel D1: O[b,q,d] = (1/sum) * sum_k exp(S-m) * V[b,k,d]   (overwrite)
// grid (TQ/64, B), 256 threads, exp fused at smem fill, f32x2 inner loop.
// thread: dg = tid&7 (8 floats of d), qr = tid>>3 (rows qr, qr+32)
// ---------------------------------------------------------------------------
extern "C" __global__ void __launch_bounds__(256)
pv_kernel(const float* __restrict__ V, float* __restrict__ Out)
{
    const int bz = blockIdx.y;
    const int qt = blockIdx.x * 64;
    const float* Vb = V + (size_t)bz * TK_ * D_;
    const float* Sb = g_S + (size_t)bz * TQ_ * TK_;

    __shared__ float Pm[64][36];    // exp'd P chunk [q][k32], padded
    __shared__ float Vs[32][68];    // V chunk [k][d], padded
    __shared__ float mxs[64], invs[64];

    const int tid = threadIdx.x;
    if (tid < 64) {
        mxs[tid]  = g_mx[bz * TQ_ + qt + tid];
        invs[tid] = g_inv[bz * TQ_ + qt + tid];
    }
    __syncthreads();

    const int dg = tid & 7;
    const int qr = tid >> 3;

    u64 acc[2][4];
#pragma unroll
    for (int i = 0; i < 2; i++)
#pragma unroll
        for (int j = 0; j < 4; j++) acc[i][j] = 0ull;

    for (int kt = 0; kt < TK_; kt += 32) {
#pragma unroll
        for (int i = 0; i < 2; i++) {
            int idx = tid + i * 256;    // 512 float4 over 64x32
            int r  = idx >> 3;
            int kc = (idx & 7) * 4;
            float4 v = *(const float4*)(Sb + (size_t)(qt + r) * TK_ + kt + kc);
            float m = mxs[r];
            float4 e = make_float4(__expf(v.x - m), __expf(v.y - m),
                                   __expf(v.z - m), __expf(v.w - m));
            *(float4*)&Pm[r][kc] = e;
        }
#pragma unroll
        for (int i = 0; i < 2; i++) {
            int idx = tid + i * 256;    // 512 float4 over 32x64
            int r  = idx >> 4;
            int dc = (idx & 15) * 4;
            *(float4*)&Vs[r][dc] = *(const float4*)(Vb + (size_t)(kt + r) * D_ + dc);
        }
        __syncthreads();
#pragma unroll 4
        for (int k = 0; k < 32; k++) {
            ulonglong2 v0 = *(const ulonglong2*)&Vs[k][dg * 8];
            ulonglong2 v1 = *(const ulonglong2*)&Vs[k][dg * 8 + 4];
            float p0 = Pm[qr][k];
            float p1 = Pm[qr + 32][k];
            u64 a0 = pack2(p0, p0);
            u64 a1 = pack2(p1, p1);
            fma2(acc[0][0], a0, v0.x); fma2(acc[0][1], a0, v0.y);
            fma2(acc[0][2], a0, v1.x); fma2(acc[0][3], a0, v1.y);
            fma2(acc[1][0], a1, v0.x); fma2(acc[1][1], a1, v0.y);
            fma2(acc[1][2], a1, v1.x); fma2(acc[1][3], a1, v1.y);
        }
        __syncthreads();
    }

#pragma unroll
    for (int i = 0; i < 2; i++) {
        const int qrow = qr + 32 * i;
        const float inv = invs[qrow];
        float2 c0 = unpack2(acc[i][0]);
        float2 c1 = unpack2(acc[i][1]);
        float2 c2 = unpack2(acc[i][2]);
        float2 c3 = unpack2(acc[i][3]);
        float* dst = Out + ((size_t)bz * TQ_ + qt + qrow) * D_ + dg * 8;
        *(float4*)(dst)     = make_float4(c0.x * inv, c0.y * inv, c1.x * inv, c1.y * inv);
        *(float4*)(dst + 4) = make_float4(c2.x * inv, c2.y * inv, c3.x * inv, c3.y * inv);
    }
}

// ---------------------------------------------------------------------------
// Kernel D2: O[b,q,d] += (1/sum) * sum_k exp(S-m) * pos_v[q,k,d]
// grid (TQ), 256 threads. pos_v read exactly once. dg = tid&7, b = tid>>3.
// ---------------------------------------------------------------------------
extern "C" __global__ void __launch_bounds__(256)
posv_kernel(const float* __restrict__ PV, float* __restrict__ Out)
{
    const int q = blockIdx.x;

    __shared__ float PVs[64][68];   // pos_v chunk [k][d], padded
    __shared__ float Pm[B_][68];    // exp'd P chunk [b][k64], padded
    __shared__ float mxs[B_], invs[B_];

    const int tid = threadIdx.x;
    if (tid < B_) {
        mxs[tid]  = g_mx[tid * TQ_ + q];
        invs[tid] = g_inv[tid * TQ_ + q];
    }
    __syncthreads();

    const int dg = tid & 7;
    const int b  = tid >> 3;

    u64 acc[4];
#pragma unroll
    for (int j = 0; j < 4; j++) acc[j] = 0ull;

    for (int kt = 0; kt < TK_; kt += 64) {
        const float* PVq = PV + ((size_t)q * TK_ + kt) * D_;
#pragma unroll
        for (int i = 0; i < 4; i++) {
            int idx = tid + i * 256;    // 1024 float4 over 64x64
            int k  = idx >> 4;
            int dc = (idx & 15) * 4;
            *(float4*)&PVs[k][dc] = *(const float4*)(PVq + (size_t)k * D_ + dc);
        }
#pragma unroll
        for (int i = 0; i < 2; i++) {
            int idx = tid + i * 256;    // 512 float4 over 32x64
            int bb = idx >> 4;
            int kc = (idx & 15) * 4;
            float4 v = *(const float4*)(g_S + ((size_t)bb * TQ_ + q) * TK_ + kt + kc);
            float m = mxs[bb];
            float4 e = make_float4(__expf(v.x - m), __expf(v.y - m),
                                   __expf(v.z - m), __expf(v.w - m));
            *(float4*)&Pm[bb][kc] = e;
        }
        __syncthreads();
#pragma unroll 4
        for (int k = 0; k < 64; k++) {
            float p = Pm[b][k];
            u64 ap = pack2(p, p);
            ulonglong2 v0 = *(const ulonglong2*)&PVs[k][dg * 8];
            ulonglong2 v1 = *(const ulonglong2*)&PVs[k][dg * 8 + 4];
            fma2(acc[0], ap, v0.x);
            fma2(acc[1], ap, v0.y);
            fma2(acc[2], ap, v1.x);
            fma2(acc[3], ap, v1.y);
        }
        __syncthreads();
    }

    const float inv = invs[b];
    float2 c0 = unpack2(acc[0]);
    float2 c1 = unpack2(acc[1]);
    float2 c2 = unpack2(acc[2]);
    float2 c3 = unpack2(acc[3]);
    float* dst = Out + ((size_t)b * TQ_ + q) * D_ + dg * 8;
    float4 o0 = *(float4*)(dst);
    float4 o1 = *(float4*)(dst + 4);
    o0.x += c0.x * inv; o0.y += c0.y * inv; o0.z += c1.x * inv; o0.w += c1.y * inv;
    o1.x += c2.x * inv; o1.y += c2.y * inv; o1.z += c3.x * inv; o1.w += c3.y * inv;
    *(float4*)(dst)     = o0;
    *(float4*)(dst + 4) = o1;
}

// ---------------------------------------------------------------------------
extern "C" void kernel_launch(void* const* d_in, const int* in_sizes, int n_in,
                              void* d_out, int out_size)
{
    const float* Q  = (const float*)d_in[0];
    const float* K  = (const float*)d_in[1];
    const float* V  = (const float*)d_in[2];
    const float* PK = (const float*)d_in[3];
    const float* PV = (const float*)d_in[4];
    const int*   VL = (const int*)d_in[5];
    float* Out = (float*)d_out;

    qk_kernel<<<dim3(TK_ / 128, TQ_ / 128, B_), 256>>>(Q, K);
    posk_kernel<<<dim3(TK_ / 128, TQ_), 256>>>(Q, PK, VL);
    stats_kernel<<<dim3(TQ_, B_), 256>>>();
    pv_kernel<<<dim3(TQ_ / 64, B_), 256>>>(V, Out);
    posv_kernel<<<TQ_, 256>>>(PV, Out);
}

// round 3
// speedup vs baseline: 2.0481x; 2.0481x over previous
#include <cuda_runtime.h>
#include <cuda_bf16.h>
#include <math.h>

typedef unsigned u32;

#define B_  32
#define TQ_ 1024
#define TK_ 1024
#define D_  64

// 134 MB scores scratch + per-row softmax stats (static device bss; no runtime alloc)
static __device__ float g_S[(size_t)B_ * TQ_ * TK_];
static __device__ float g_mx[B_ * TQ_];
static __device__ float g_inv[B_ * TQ_];

// ---- bf16 mma + error-split helpers ---------------------------------------
__device__ __forceinline__ void mma_bf16(float c[4], u32 a0, u32 a1, u32 a2, u32 a3,
                                         u32 b0, u32 b1)
{
    asm volatile(
        "mma.sync.aligned.m16n8k16.row.col.f32.bf16.bf16.f32 "
        "{%0,%1,%2,%3},{%4,%5,%6,%7},{%8,%9},{%0,%1,%2,%3};\n"
        : "+f"(c[0]), "+f"(c[1]), "+f"(c[2]), "+f"(c[3])
        : "r"(a0), "r"(a1), "r"(a2), "r"(a3), "r"(b0), "r"(b1));
}

__device__ __forceinline__ void split_store(float x, __nv_bfloat16* ph, __nv_bfloat16* pl)
{
    __nv_bfloat16 h = __float2bfloat16(x);
    *ph = h;
    *pl = __float2bfloat16(x - __bfloat162float(h));
}

#define STRD 72   // smem row stride in bf16 elems (64 data + 8 pad; conflict-free frags)

// ---------------------------------------------------------------------------
// Kernel A: content scores S[b,q,k] = Q[b,q,:]·K[b,k,:]  (unscaled, overwrite)
// grid (16,16,32), 256 thr. Block tile 64x64, warp tile 32x16, 3-phase bf16x3.
// ---------------------------------------------------------------------------
extern "C" __global__ void __launch_bounds__(256)
qk_kernel(const float* __restrict__ Q, const float* __restrict__ K)
{
    const int bz = blockIdx.z;
    const int qt = blockIdx.y * 64;
    const int kt = blockIdx.x * 64;
    const float* Qb = Q + (size_t)bz * TQ_ * D_;
    const float* Kb = K + (size_t)bz * TK_ * D_;
    float* Sb = g_S + (size_t)bz * TQ_ * TK_;

    __shared__ __nv_bfloat16 Ah[64][STRD], Al[64][STRD];
    __shared__ __nv_bfloat16 Bh[64][STRD], Bl[64][STRD];

    const int tid = threadIdx.x;
#pragma unroll
    for (int i = 0; i < 4; i++) {
        int t4  = tid + i * 256;       // 1024 float4 over 64x64
        int row = t4 >> 4;
        int col = (t4 & 15) * 4;
        float4 v = *(const float4*)(Qb + (size_t)(qt + row) * D_ + col);
        split_store(v.x, &Ah[row][col + 0], &Al[row][col + 0]);
        split_store(v.y, &Ah[row][col + 1], &Al[row][col + 1]);
        split_store(v.z, &Ah[row][col + 2], &Al[row][col + 2]);
        split_store(v.w, &Ah[row][col + 3], &Al[row][col + 3]);
        float4 w = *(const float4*)(Kb + (size_t)(kt + row) * D_ + col);
        split_store(w.x, &Bh[row][col + 0], &Bl[row][col + 0]);
        split_store(w.y, &Bh[row][col + 1], &Bl[row][col + 1]);
        split_store(w.z, &Bh[row][col + 2], &Bl[row][col + 2]);
        split_store(w.w, &Bh[row][col + 3], &Bl[row][col + 3]);
    }
    __syncthreads();

    const int wid = tid >> 5, lane = tid & 31;
    const int g = lane >> 2, tg = lane & 3;
    const int wm = (wid >> 2) * 32;    // 0 or 32
    const int wn = (wid & 3) * 16;     // 0..48

    float c[2][2][4] = {};

#pragma unroll
    for (int ph = 0; ph < 3; ph++) {
        const __nv_bfloat16* Ap = (ph == 1) ? &Al[0][0] : &Ah[0][0];
        const __nv_bfloat16* Bp = (ph == 2) ? &Bl[0][0] : &Bh[0][0];
#pragma unroll
        for (int k0 = 0; k0 < 64; k0 += 16) {
            u32 a[2][4], b[2][2];
#pragma unroll
            for (int mi = 0; mi < 2; mi++) {
                const __nv_bfloat16* base = Ap + (wm + mi * 16 + g) * STRD + k0 + 2 * tg;
                a[mi][0] = *(const u32*)(base);
                a[mi][1] = *(const u32*)(base + 8 * STRD);
                a[mi][2] = *(const u32*)(base + 8);
                a[mi][3] = *(const u32*)(base + 8 * STRD + 8);
            }
#pragma unroll
            for (int ni = 0; ni < 2; ni++) {
                const __nv_bfloat16* base = Bp + (wn + ni * 8 + g) * STRD + k0 + 2 * tg;
                b[ni][0] = *(const u32*)(base);
                b[ni][1] = *(const u32*)(base + 8);
            }
#pragma unroll
            for (int mi = 0; mi < 2; mi++)
#pragma unroll
                for (int ni = 0; ni < 2; ni++)
                    mma_bf16(c[mi][ni], a[mi][0], a[mi][1], a[mi][2], a[mi][3],
                             b[ni][0], b[ni][1]);
        }
    }

#pragma unroll
    for (int mi = 0; mi < 2; mi++)
#pragma unroll
        for (int ni = 0; ni < 2; ni++) {
            int m = qt + wm + mi * 16 + g;
            int n = kt + wn + ni * 8 + 2 * tg;
            *(float2*)&Sb[(size_t)m * TK_ + n] =
                make_float2(c[mi][ni][0], c[mi][ni][1]);
            *(float2*)&Sb[(size_t)(m + 8) * TK_ + n] =
                make_float2(c[mi][ni][2], c[mi][ni][3]);
        }
}

// ---------------------------------------------------------------------------
// Kernel B: S = mask( (S + Q[b,q,:]·pos_k[q,k,:]) / 8 )
// grid (8, 1024), 256 thr. M=32(batch), N=128(k), pos_k read exactly once.
// ---------------------------------------------------------------------------
extern "C" __global__ void __launch_bounds__(256)
posk_kernel(const float* __restrict__ Q, const float* __restrict__ PK,
            const int* __restrict__ VL)
{
    const int q  = blockIdx.y;
    const int kt = blockIdx.x * 128;

    __shared__ __nv_bfloat16 Ah[32][STRD], Al[32][STRD];    // Q[:,q,:]
    __shared__ __nv_bfloat16 Bh[128][STRD], Bl[128][STRD];  // pos_k chunk
    __shared__ int vls[B_];

    const int tid = threadIdx.x;
#pragma unroll
    for (int i = 0; i < 2; i++) {
        int t4  = tid + i * 256;       // 512 float4 over 32x64
        int row = t4 >> 4;
        int col = (t4 & 15) * 4;
        float4 v = *(const float4*)(Q + ((size_t)row * TQ_ + q) * D_ + col);
        split_store(v.x, &Ah[row][col + 0], &Al[row][col + 0]);
        split_store(v.y, &Ah[row][col + 1], &Al[row][col + 1]);
        split_store(v.z, &Ah[row][col + 2], &Al[row][col + 2]);
        split_store(v.w, &Ah[row][col + 3], &Al[row][col + 3]);
    }
    const float* PKq = PK + ((size_t)q * TK_ + kt) * D_;
#pragma unroll
    for (int i = 0; i < 8; i++) {
        int t4  = tid + i * 256;       // 2048 float4 over 128x64
        int row = t4 >> 4;
        int col = (t4 & 15) * 4;
        float4 v = *(const float4*)(PKq + (size_t)row * D_ + col);
        split_store(v.x, &Bh[row][col + 0], &Bl[row][col + 0]);
        split_store(v.y, &Bh[row][col + 1], &Bl[row][col + 1]);
        split_store(v.z, &Bh[row][col + 2], &Bl[row][col + 2]);
        split_store(v.w, &Bh[row][col + 3], &Bl[row][col + 3]);
    }
    if (tid < B_) vls[tid] = VL[tid];
    __syncthreads();

    const int wid = tid >> 5, lane = tid & 31;
    const int g = lane >> 2, tg = lane & 3;
    const int wn = wid * 16;

    float c[2][2][4] = {};

#pragma unroll
    for (int ph = 0; ph < 3; ph++) {
        const __nv_bfloat16* Ap = (ph == 1) ? &Al[0][0] : &Ah[0][0];
        const __nv_bfloat16* Bp = (ph == 2) ? &Bl[0][0] : &Bh[0][0];
#pragma unroll
        for (int k0 = 0; k0 < 64; k0 += 16) {
            u32 a[2][4], b[2][2];
#pragma unroll
            for (int mi = 0; mi < 2; mi++) {
                const __nv_bfloat16* base = Ap + (mi * 16 + g) * STRD + k0 + 2 * tg;
                a[mi][0] = *(const u32*)(base);
                a[mi][1] = *(const u32*)(base + 8 * STRD);
                a[mi][2] = *(const u32*)(base + 8);
                a[mi][3] = *(const u32*)(base + 8 * STRD + 8);
            }
#pragma unroll
            for (int ni = 0; ni < 2; ni++) {
                const __nv_bfloat16* base = Bp + (wn + ni * 8 + g) * STRD + k0 + 2 * tg;
                b[ni][0] = *(const u32*)(base);
                b[ni][1] = *(const u32*)(base + 8);
            }
#pragma unroll
            for (int mi = 0; mi < 2; mi++)
#pragma unroll
                for (int ni = 0; ni < 2; ni++)
                    mma_bf16(c[mi][ni], a[mi][0], a[mi][1], a[mi][2], a[mi][3],
                             b[ni][0], b[ni][1]);
        }
    }

#pragma unroll
    for (int mi = 0; mi < 2; mi++) {
        const int b0  = mi * 16 + g;
        const int b1  = b0 + 8;
        const int vl0 = vls[b0];
        const int vl1 = vls[b1];
#pragma unroll
        for (int ni = 0; ni < 2; ni++) {
            const int col = kt + wn + ni * 8 + 2 * tg;
            float* p0 = &g_S[((size_t)b0 * TQ_ + q) * TK_ + col];
            float2 s0 = *(float2*)p0;
            s0.x = (col     < vl0) ? (s0.x + c[mi][ni][0]) * 0.125f : -1e6f;
            s0.y = (col + 1 < vl0) ? (s0.y + c[mi][ni][1]) * 0.125f : -1e6f;
            *(float2*)p0 = s0;
            float* p1 = &g_S[((size_t)b1 * TQ_ + q) * TK_ + col];
            float2 s1 = *(float2*)p1;
            s1.x = (col     < vl1) ? (s1.x + c[mi][ni][2]) * 0.125f : -1e6f;
            s1.y = (col + 1 < vl1) ? (s1.y + c[mi][ni][3]) * 0.125f : -1e6f;
            *(float2*)p1 = s1;
        }
    }
}

// ---------------------------------------------------------------------------
// Kernel C: row softmax stats: g_mx = rowmax, g_inv = 1/sum(exp(s-m))
// ---------------------------------------------------------------------------
extern "C" __global__ void __launch_bounds__(256)
stats_kernel()
{
    const int q = blockIdx.x;
    const int b = blockIdx.y;
    const float* row = g_S + ((size_t)b * TQ_ + q) * TK_;
    const int tid = threadIdx.x;

    float4 v = *(const float4*)&row[tid * 4];
    float m = fmaxf(fmaxf(v.x, v.y), fmaxf(v.z, v.w));
#pragma unroll
    for (int o = 16; o > 0; o >>= 1) m = fmaxf(m, __shfl_xor_sync(0xffffffffu, m, o));

    __shared__ float red[8];
    if ((tid & 31) == 0) red[tid >> 5] = m;
    __syncthreads();
    float M = red[0];
#pragma unroll
    for (int i = 1; i < 8; i++) M = fmaxf(M, red[i]);

    float s = (__expf(v.x - M) + __expf(v.y - M)) +
              (__expf(v.z - M) + __expf(v.w - M));
#pragma unroll
    for (int o = 16; o > 0; o >>= 1) s += __shfl_xor_sync(0xffffffffu, s, o);
    __syncthreads();
    if ((tid & 31) == 0) red[tid >> 5] = s;
    __syncthreads();
    if (tid == 0) {
        float tot = 0.f;
#pragma unroll
        for (int i = 0; i < 8; i++) tot += red[i];
        g_mx[b * TQ_ + q]  = M;
        g_inv[b * TQ_ + q] = 1.0f / tot;
    }
}

// ---------------------------------------------------------------------------
// Kernel D1: O = (1/sum) * exp(S-m) · V   (overwrite). grid (16,32), 256 thr.
// Block tile M=64 q-rows, N=64 d. k_seq chunks of 64, exp fused at smem fill.
// ---------------------------------------------------------------------------
extern "C" __global__ void __launch_bounds__(256)
pv_kernel(const float* __restrict__ V, float* __restrict__ Out)
{
    const int bz = blockIdx.y;
    const int qt = blockIdx.x * 64;
    const float* Vb = V + (size_t)bz * TK_ * D_;
    const float* Sb = g_S + (size_t)bz * TQ_ * TK_;

    __shared__ __nv_bfloat16 Ah[64][STRD], Al[64][STRD];  // exp'd P chunk
    __shared__ __nv_bfloat16 Bh[64][STRD], Bl[64][STRD];  // V chunk, [d][k]
    __shared__ float mxs[64], invs[64];

    const int tid = threadIdx.x;
    if (tid < 64) {
        mxs[tid]  = g_mx[bz * TQ_ + qt + tid];
        invs[tid] = g_inv[bz * TQ_ + qt + tid];
    }
    __syncthreads();

    const int wid = tid >> 5, lane = tid & 31;
    const int g = lane >> 2, tg = lane & 3;
    const int wm = (wid >> 2) * 32;
    const int wn = (wid & 3) * 16;

    float c[2][2][4] = {};

    for (int kt = 0; kt < TK_; kt += 64) {
#pragma unroll
        for (int i = 0; i < 4; i++) {
            int t4 = tid + i * 256;      // 1024 float4 over 64(q)x64(k)
            int r  = t4 >> 4;
            int kc = (t4 & 15) * 4;
            float4 s = *(const float4*)(Sb + (size_t)(qt + r) * TK_ + kt + kc);
            float m = mxs[r];
            split_store(__expf(s.x - m), &Ah[r][kc + 0], &Al[r][kc + 0]);
            split_store(__expf(s.y - m), &Ah[r][kc + 1], &Al[r][kc + 1]);
            split_store(__expf(s.z - m), &Ah[r][kc + 2], &Al[r][kc + 2]);
            split_store(__expf(s.w - m), &Ah[r][kc + 3], &Al[r][kc + 3]);
        }
#pragma unroll
        for (int i = 0; i < 4; i++) {
            int t4 = tid + i * 256;      // 1024 float4 over 64(k)x64(d), transpose
            int k  = t4 >> 4;
            int dc = (t4 & 15) * 4;
            float4 v = *(const float4*)(Vb + (size_t)(kt + k) * D_ + dc);
            split_store(v.x, &Bh[dc + 0][k], &Bl[dc + 0][k]);
            split_store(v.y, &Bh[dc + 1][k], &Bl[dc + 1][k]);
            split_store(v.z, &Bh[dc + 2][k], &Bl[dc + 2][k]);
            split_store(v.w, &Bh[dc + 3][k], &Bl[dc + 3][k]);
        }
        __syncthreads();

#pragma unroll
        for (int ph = 0; ph < 3; ph++) {
            const __nv_bfloat16* Ap = (ph == 1) ? &Al[0][0] : &Ah[0][0];
            const __nv_bfloat16* Bp = (ph == 2) ? &Bl[0][0] : &Bh[0][0];
#pragma unroll
            for (int k0 = 0; k0 < 64; k0 += 16) {
                u32 a[2][4], b[2][2];
#pragma unroll
                for (int mi = 0; mi < 2; mi++) {
                    const __nv_bfloat16* base = Ap + (wm + mi * 16 + g) * STRD + k0 + 2 * tg;
                    a[mi][0] = *(const u32*)(base);
                    a[mi][1] = *(const u32*)(base + 8 * STRD);
                    a[mi][2] = *(const u32*)(base + 8);
                    a[mi][3] = *(const u32*)(base + 8 * STRD + 8);
                }
#pragma unroll
                for (int ni = 0; ni < 2; ni++) {
                    const __nv_bfloat16* base = Bp + (wn + ni * 8 + g) * STRD + k0 + 2 * tg;
                    b[ni][0] = *(const u32*)(base);
                    b[ni][1] = *(const u32*)(base + 8);
                }
#pragma unroll
                for (int mi = 0; mi < 2; mi++)
#pragma unroll
                    for (int ni = 0; ni < 2; ni++)
                        mma_bf16(c[mi][ni], a[mi][0], a[mi][1], a[mi][2], a[mi][3],
                                 b[ni][0], b[ni][1]);
            }
        }
        __syncthreads();
    }

#pragma unroll
    for (int mi = 0; mi < 2; mi++)
#pragma unroll
        for (int ni = 0; ni < 2; ni++) {
            int m = wm + mi * 16 + g;
            int n = wn + ni * 8 + 2 * tg;
            float inv0 = invs[m], inv1 = invs[m + 8];
            float* d0 = Out + ((size_t)bz * TQ_ + qt + m) * D_ + n;
            *(float2*)d0 = make_float2(c[mi][ni][0] * inv0, c[mi][ni][1] * inv0);
            float* d1 = Out + ((size_t)bz * TQ_ + qt + m + 8) * D_ + n;
            *(float2*)d1 = make_float2(c[mi][ni][2] * inv1, c[mi][ni][3] * inv1);
        }
}

// ---------------------------------------------------------------------------
// Kernel D2: O += (1/sum) * exp(S-m) · pos_v[q]   grid (1024), 256 thr.
// M=32(batch), N=64(d), pos_v read exactly once.
// ---------------------------------------------------------------------------
extern "C" __global__ void __launch_bounds__(256)
posv_kernel(const float* __restrict__ PV, float* __restrict__ Out)
{
    const int q = blockIdx.x;

    __shared__ __nv_bfloat16 Ah[32][STRD], Al[32][STRD];   // exp'd P chunk
    __shared__ __nv_bfloat16 Bh[64][STRD], Bl[64][STRD];   // pos_v chunk [d][k]
    __shared__ float mxs[B_], invs[B_];

    const int tid = threadIdx.x;
    if (tid < B_) {
        mxs[tid]  = g_mx[tid * TQ_ + q];
        invs[tid] = g_inv[tid * TQ_ + q];
    }
    __syncthreads();

    const int wid = tid >> 5, lane = tid & 31;
    const int g = lane >> 2, tg = lane & 3;
    const int wn = wid * 8;

    float c[2][4] = {};

    for (int kt = 0; kt < TK_; kt += 64) {
#pragma unroll
        for (int i = 0; i < 2; i++) {
            int t4 = tid + i * 256;      // 512 float4 over 32(b)x64(k)
            int bb = t4 >> 4;
            int kc = (t4 & 15) * 4;
            float4 s = *(const float4*)(g_S + ((size_t)bb * TQ_ + q) * TK_ + kt + kc);
            float m = mxs[bb];
            split_store(__expf(s.x - m), &Ah[bb][kc + 0], &Al[bb][kc + 0]);
            split_store(__expf(s.y - m), &Ah[bb][kc + 1], &Al[bb][kc + 1]);
            split_store(__expf(s.z - m), &Ah[bb][kc + 2], &Al[bb][kc + 2]);
            split_store(__expf(s.w - m), &Ah[bb][kc + 3], &Al[bb][kc + 3]);
        }
        const float* PVq = PV + ((size_t)q * TK_ + kt) * D_;
#pragma unroll
        for (int i = 0; i < 4; i++) {
            int t4 = tid + i * 256;      // 1024 float4 over 64(k)x64(d), transpose
            int k  = t4 >> 4;
            int dc = (t4 & 15) * 4;
            float4 v = *(const float4*)(PVq + (size_t)k * D_ + dc);
            split_store(v.x, &Bh[dc + 0][k], &Bl[dc + 0][k]);
            split_store(v.y, &Bh[dc + 1][k], &Bl[dc + 1][k]);
            split_store(v.z, &Bh[dc + 2][k], &Bl[dc + 2][k]);
            split_store(v.w, &Bh[dc + 3][k], &Bl[dc + 3][k]);
        }
        __syncthreads();

#pragma unroll
        for (int ph = 0; ph < 3; ph++) {
            const __nv_bfloat16* Ap = (ph == 1) ? &Al[0][0] : &Ah[0][0];
            const __nv_bfloat16* Bp = (ph == 2) ? &Bl[0][0] : &Bh[0][0];
#pragma unroll
            for (int k0 = 0; k0 < 64; k0 += 16) {
                u32 a[2][4], b[2];
#pragma unroll
                for (int mi = 0; mi < 2; mi++) {
                    const __nv_bfloat16* base = Ap + (mi * 16 + g) * STRD + k0 + 2 * tg;
                    a[mi][0] = *(const u32*)(base);
                    a[mi][1] = *(const u32*)(base + 8 * STRD);
                    a[mi][2] = *(const u32*)(base + 8);
                    a[mi][3] = *(const u32*)(base + 8 * STRD + 8);
                }
                {
                    const __nv_bfloat16* base = Bp + (wn + g) * STRD + k0 + 2 * tg;
                    b[0] = *(const u32*)(base);
                    b[1] = *(const u32*)(base + 8);
                }
#pragma unroll
                for (int mi = 0; mi < 2; mi++)
                    mma_bf16(c[mi], a[mi][0], a[mi][1], a[mi][2], a[mi][3], b[0], b[1]);
            }
        }
        __syncthreads();
    }

#pragma unroll
    for (int mi = 0; mi < 2; mi++) {
        const int b0 = mi * 16 + g;
        const int b1 = b0 + 8;
        const int n  = wn + 2 * tg;
        float* d0 = Out + ((size_t)b0 * TQ_ + q) * D_ + n;
        float2 o0 = *(float2*)d0;
        o0.x += c[mi][0] * invs[b0];
        o0.y += c[mi][1] * invs[b0];
        *(float2*)d0 = o0;
        float* d1 = Out + ((size_t)b1 * TQ_ + q) * D_ + n;
        float2 o1 = *(float2*)d1;
        o1.x += c[mi][2] * invs[b1];
        o1.y += c[mi][3] * invs[b1];
        *(float2*)d1 = o1;
    }
}

// ---------------------------------------------------------------------------
extern "C" void kernel_launch(void* const* d_in, const int* in_sizes, int n_in,
                              void* d_out, int out_size)
{
    const float* Q  = (const float*)d_in[0];
    const float* K  = (const float*)d_in[1];
    const float* V  = (const float*)d_in[2];
    const float* PK = (const float*)d_in[3];
    const float* PV = (const float*)d_in[4];
    const int*   VL = (const int*)d_in[5];
    float* Out = (float*)d_out;

    qk_kernel<<<dim3(TK_ / 64, TQ_ / 64, B_), 256>>>(Q, K);
    posk_kernel<<<dim3(TK_ / 128, TQ_), 256>>>(Q, PK, VL);
    stats_kernel<<<dim3(TQ_, B_), 256>>>();
    pv_kernel<<<dim3(TQ_ / 64, B_), 256>>>(V, Out);
    posv_kernel<<<TQ_, 256>>>(PV, Out);
}

// round 4
// speedup vs baseline: 3.1622x; 1.5440x over previous
#include <cuda_runtime.h>
#include <cuda_bf16.h>
#include <math.h>

typedef unsigned u32;

#define B_  32
#define TQ_ 1024
#define TK_ 1024
#define D_  64
#define STRD 72   // bf16 smem row stride (64 data + 8 pad): conflict-free frag LDS

// 134 MB scores scratch + softmax stats (static device bss; no runtime alloc)
static __device__ float g_S[(size_t)B_ * TQ_ * TK_];
static __device__ float g_mx[B_ * TQ_];
static __device__ float g_inv[B_ * TQ_];

// ---- bf16 mma + packed split helpers --------------------------------------
__device__ __forceinline__ void mma_bf16(float c[4], u32 a0, u32 a1, u32 a2, u32 a3,
                                         u32 b0, u32 b1)
{
    asm volatile(
        "mma.sync.aligned.m16n8k16.row.col.f32.bf16.bf16.f32 "
        "{%0,%1,%2,%3},{%4,%5,%6,%7},{%8,%9},{%0,%1,%2,%3};\n"
        : "+f"(c[0]), "+f"(c[1]), "+f"(c[2]), "+f"(c[3])
        : "r"(a0), "r"(a1), "r"(a2), "r"(a3), "r"(b0), "r"(b1));
}

__device__ __forceinline__ u32 cvt2(float hi, float lo) {
    u32 r;
    asm("cvt.rn.bf16x2.f32 %0,%1,%2;" : "=r"(r) : "f"(hi), "f"(lo));
    return r;
}
// x0 -> low bf16, x1 -> high bf16; h = packed hi parts, l = packed residuals
__device__ __forceinline__ void split2(float x0, float x1, u32& h, u32& l) {
    h = cvt2(x1, x0);
    float h0 = __uint_as_float(h << 16);          // exact bf16->f32
    float h1 = __uint_as_float(h & 0xffff0000u);
    l = cvt2(x1 - h1, x0 - h0);
}

// ---------------------------------------------------------------------------
// Kernel A: S[b,q,k] = Q[b,q,:]·K[b,k,:] (unscaled). grid (16,16,32), 256 thr.
// ---------------------------------------------------------------------------
extern "C" __global__ void __launch_bounds__(256)
qk_kernel(const float* __restrict__ Q, const float* __restrict__ K)
{
    const int bz = blockIdx.z;
    const int qt = blockIdx.y * 64;
    const int kt = blockIdx.x * 64;
    const float* Qb = Q + (size_t)bz * TQ_ * D_;
    const float* Kb = K + (size_t)bz * TK_ * D_;
    float* Sb = g_S + (size_t)bz * TQ_ * TK_;

    __shared__ __nv_bfloat16 Ah[64][STRD], Al[64][STRD];
    __shared__ __nv_bfloat16 Bh[64][STRD], Bl[64][STRD];

    const int tid = threadIdx.x;
#pragma unroll
    for (int i = 0; i < 4; i++) {
        int t4  = tid + i * 256;
        int row = t4 >> 4;
        int col = (t4 & 15) * 4;
        float4 v = *(const float4*)(Qb + (size_t)(qt + row) * D_ + col);
        u32 h0, l0, h1, l1;
        split2(v.x, v.y, h0, l0); split2(v.z, v.w, h1, l1);
        *(uint2*)&Ah[row][col] = make_uint2(h0, h1);
        *(uint2*)&Al[row][col] = make_uint2(l0, l1);
        float4 w = *(const float4*)(Kb + (size_t)(kt + row) * D_ + col);
        split2(w.x, w.y, h0, l0); split2(w.z, w.w, h1, l1);
        *(uint2*)&Bh[row][col] = make_uint2(h0, h1);
        *(uint2*)&Bl[row][col] = make_uint2(l0, l1);
    }
    __syncthreads();

    const int wid = tid >> 5, lane = tid & 31;
    const int g = lane >> 2, tg = lane & 3;
    const int wm = (wid >> 2) * 32;
    const int wn = (wid & 3) * 16;

    float c[2][2][4] = {};

#pragma unroll
    for (int k0 = 0; k0 < 64; k0 += 16) {
        u32 ah[2][4], al[2][4], bh[2][2], bl[2][2];
#pragma unroll
        for (int mi = 0; mi < 2; mi++) {
            const __nv_bfloat16* ph = &Ah[wm + mi * 16 + g][k0 + 2 * tg];
            ah[mi][0] = *(const u32*)(ph);
            ah[mi][1] = *(const u32*)(ph + 8 * STRD);
            ah[mi][2] = *(const u32*)(ph + 8);
            ah[mi][3] = *(const u32*)(ph + 8 * STRD + 8);
            const __nv_bfloat16* pl = &Al[wm + mi * 16 + g][k0 + 2 * tg];
            al[mi][0] = *(const u32*)(pl);
            al[mi][1] = *(const u32*)(pl + 8 * STRD);
            al[mi][2] = *(const u32*)(pl + 8);
            al[mi][3] = *(const u32*)(pl + 8 * STRD + 8);
        }
#pragma unroll
        for (int ni = 0; ni < 2; ni++) {
            const __nv_bfloat16* ph = &Bh[wn + ni * 8 + g][k0 + 2 * tg];
            bh[ni][0] = *(const u32*)(ph);
            bh[ni][1] = *(const u32*)(ph + 8);
            const __nv_bfloat16* pl = &Bl[wn + ni * 8 + g][k0 + 2 * tg];
            bl[ni][0] = *(const u32*)(pl);
            bl[ni][1] = *(const u32*)(pl + 8);
        }
#pragma unroll
        for (int mi = 0; mi < 2; mi++)
#pragma unroll
            for (int ni = 0; ni < 2; ni++) {
                mma_bf16(c[mi][ni], ah[mi][0], ah[mi][1], ah[mi][2], ah[mi][3],
                         bh[ni][0], bh[ni][1]);
                mma_bf16(c[mi][ni], al[mi][0], al[mi][1], al[mi][2], al[mi][3],
                         bh[ni][0], bh[ni][1]);
                mma_bf16(c[mi][ni], ah[mi][0], ah[mi][1], ah[mi][2], ah[mi][3],
                         bl[ni][0], bl[ni][1]);
            }
    }

#pragma unroll
    for (int mi = 0; mi < 2; mi++)
#pragma unroll
        for (int ni = 0; ni < 2; ni++) {
            int m = qt + wm + mi * 16 + g;
            int n = kt + wn + ni * 8 + 2 * tg;
            *(float2*)&Sb[(size_t)m * TK_ + n] =
                make_float2(c[mi][ni][0], c[mi][ni][1]);
            *(float2*)&Sb[(size_t)(m + 8) * TK_ + n] =
                make_float2(c[mi][ni][2], c[mi][ni][3]);
        }
}

// ---------------------------------------------------------------------------
// Kernel B: S = mask( (S + Q[b,q,:]·pos_k[q,k,:]) / 8 ). grid (8,1024).
// ---------------------------------------------------------------------------
extern "C" __global__ void __launch_bounds__(256)
posk_kernel(const float* __restrict__ Q, const float* __restrict__ PK,
            const int* __restrict__ VL)
{
    const int q  = blockIdx.y;
    const int kt = blockIdx.x * 128;

    __shared__ __nv_bfloat16 Ah[32][STRD], Al[32][STRD];
    __shared__ __nv_bfloat16 Bh[128][STRD], Bl[128][STRD];
    __shared__ int vls[B_];

    const int tid = threadIdx.x;
#pragma unroll
    for (int i = 0; i < 2; i++) {
        int t4  = tid + i * 256;
        int row = t4 >> 4;
        int col = (t4 & 15) * 4;
        float4 v = *(const float4*)(Q + ((size_t)row * TQ_ + q) * D_ + col);
        u32 h0, l0, h1, l1;
        split2(v.x, v.y, h0, l0); split2(v.z, v.w, h1, l1);
        *(uint2*)&Ah[row][col] = make_uint2(h0, h1);
        *(uint2*)&Al[row][col] = make_uint2(l0, l1);
    }
    const float* PKq = PK + ((size_t)q * TK_ + kt) * D_;
#pragma unroll
    for (int i = 0; i < 8; i++) {
        int t4  = tid + i * 256;
        int row = t4 >> 4;
        int col = (t4 & 15) * 4;
        float4 v = *(const float4*)(PKq + (size_t)row * D_ + col);
        u32 h0, l0, h1, l1;
        split2(v.x, v.y, h0, l0); split2(v.z, v.w, h1, l1);
        *(uint2*)&Bh[row][col] = make_uint2(h0, h1);
        *(uint2*)&Bl[row][col] = make_uint2(l0, l1);
    }
    if (tid < B_) vls[tid] = VL[tid];
    __syncthreads();

    const int wid = tid >> 5, lane = tid & 31;
    const int g = lane >> 2, tg = lane & 3;
    const int wn = wid * 16;

    float c[2][2][4] = {};

#pragma unroll
    for (int k0 = 0; k0 < 64; k0 += 16) {
        u32 ah[2][4], al[2][4], bh[2][2], bl[2][2];
#pragma unroll
        for (int mi = 0; mi < 2; mi++) {
            const __nv_bfloat16* ph = &Ah[mi * 16 + g][k0 + 2 * tg];
            ah[mi][0] = *(const u32*)(ph);
            ah[mi][1] = *(const u32*)(ph + 8 * STRD);
            ah[mi][2] = *(const u32*)(ph + 8);
            ah[mi][3] = *(const u32*)(ph + 8 * STRD + 8);
            const __nv_bfloat16* pl = &Al[mi * 16 + g][k0 + 2 * tg];
            al[mi][0] = *(const u32*)(pl);
            al[mi][1] = *(const u32*)(pl + 8 * STRD);
            al[mi][2] = *(const u32*)(pl + 8);
            al[mi][3] = *(const u32*)(pl + 8 * STRD + 8);
        }
#pragma unroll
        for (int ni = 0; ni < 2; ni++) {
            const __nv_bfloat16* ph = &Bh[wn + ni * 8 + g][k0 + 2 * tg];
            bh[ni][0] = *(const u32*)(ph);
            bh[ni][1] = *(const u32*)(ph + 8);
            const __nv_bfloat16* pl = &Bl[wn + ni * 8 + g][k0 + 2 * tg];
            bl[ni][0] = *(const u32*)(pl);
            bl[ni][1] = *(const u32*)(pl + 8);
        }
#pragma unroll
        for (int mi = 0; mi < 2; mi++)
#pragma unroll
            for (int ni = 0; ni < 2; ni++) {
                mma_bf16(c[mi][ni], ah[mi][0], ah[mi][1], ah[mi][2], ah[mi][3],
                         bh[ni][0], bh[ni][1]);
                mma_bf16(c[mi][ni], al[mi][0], al[mi][1], al[mi][2], al[mi][3],
                         bh[ni][0], bh[ni][1]);
                mma_bf16(c[mi][ni], ah[mi][0], ah[mi][1], ah[mi][2], ah[mi][3],
                         bl[ni][0], bl[ni][1]);
            }
    }

#pragma unroll
    for (int mi = 0; mi < 2; mi++) {
        const int b0  = mi * 16 + g;
        const int b1  = b0 + 8;
        const int vl0 = vls[b0];
        const int vl1 = vls[b1];
#pragma unroll
        for (int ni = 0; ni < 2; ni++) {
            const int col = kt + wn + ni * 8 + 2 * tg;
            float* p0 = &g_S[((size_t)b0 * TQ_ + q) * TK_ + col];
            float2 s0 = *(float2*)p0;
            s0.x = (col     < vl0) ? (s0.x + c[mi][ni][0]) * 0.125f : -1e6f;
            s0.y = (col + 1 < vl0) ? (s0.y + c[mi][ni][1]) * 0.125f : -1e6f;
            *(float2*)p0 = s0;
            float* p1 = &g_S[((size_t)b1 * TQ_ + q) * TK_ + col];
            float2 s1 = *(float2*)p1;
            s1.x = (col     < vl1) ? (s1.x + c[mi][ni][2]) * 0.125f : -1e6f;
            s1.y = (col + 1 < vl1) ? (s1.y + c[mi][ni][3]) * 0.125f : -1e6f;
            *(float2*)p1 = s1;
        }
    }
}

// ---------------------------------------------------------------------------
// Kernel C: row softmax stats. grid (1024, 32), 256 thr.
// ---------------------------------------------------------------------------
extern "C" __global__ void __launch_bounds__(256)
stats_kernel()
{
    const int q = blockIdx.x;
    const int b = blockIdx.y;
    const float* row = g_S + ((size_t)b * TQ_ + q) * TK_;
    const int tid = threadIdx.x;

    float4 v = *(const float4*)&row[tid * 4];
    float m = fmaxf(fmaxf(v.x, v.y), fmaxf(v.z, v.w));
#pragma unroll
    for (int o = 16; o > 0; o >>= 1) m = fmaxf(m, __shfl_xor_sync(0xffffffffu, m, o));

    __shared__ float red[8];
    if ((tid & 31) == 0) red[tid >> 5] = m;
    __syncthreads();
    float M = red[0];
#pragma unroll
    for (int i = 1; i < 8; i++) M = fmaxf(M, red[i]);

    float s = (__expf(v.x - M) + __expf(v.y - M)) +
              (__expf(v.z - M) + __expf(v.w - M));
#pragma unroll
    for (int o = 16; o > 0; o >>= 1) s += __shfl_xor_sync(0xffffffffu, s, o);
    __syncthreads();
    if ((tid & 31) == 0) red[tid >> 5] = s;
    __syncthreads();
    if (tid == 0) {
        float tot = 0.f;
#pragma unroll
        for (int i = 0; i < 8; i++) tot += red[i];
        g_mx[b * TQ_ + q]  = M;
        g_inv[b * TQ_ + q] = 1.0f / tot;
    }
}

// ---------------------------------------------------------------------------
// Kernel D1: O = (1/sum)*exp(S-m)·V. grid (16,32). V tile kept fp32 in smem;
// B fragments built with conflict-free scalar LDS + in-register split.
// ---------------------------------------------------------------------------
extern "C" __global__ void __launch_bounds__(256)
pv_kernel(const float* __restrict__ V, float* __restrict__ Out)
{
    const int bz = blockIdx.y;
    const int qt = blockIdx.x * 64;
    const float* Vb = V + (size_t)bz * TK_ * D_;
    const float* Sb = g_S + (size_t)bz * TQ_ * TK_;

    __shared__ __nv_bfloat16 Ah[64][STRD], Al[64][STRD];  // exp'd P
    __shared__ float Vs[64][68];                          // V chunk fp32 [k][d]
    __shared__ float mxs[64], invs[64];

    const int tid = threadIdx.x;
    if (tid < 64) {
        mxs[tid]  = g_mx[bz * TQ_ + qt + tid];
        invs[tid] = g_inv[bz * TQ_ + qt + tid];
    }
    __syncthreads();

    const int wid = tid >> 5, lane = tid & 31;
    const int g = lane >> 2, tg = lane & 3;
    const int wm = (wid >> 2) * 32;
    const int wn = (wid & 3) * 16;

    float c[2][2][4] = {};

    for (int kt = 0; kt < TK_; kt += 64) {
#pragma unroll
        for (int i = 0; i < 4; i++) {
            int t4 = tid + i * 256;
            int r  = t4 >> 4;
            int kc = (t4 & 15) * 4;
            float4 s = *(const float4*)(Sb + (size_t)(qt + r) * TK_ + kt + kc);
            float m = mxs[r];
            u32 h0, l0, h1, l1;
            split2(__expf(s.x - m), __expf(s.y - m), h0, l0);
            split2(__expf(s.z - m), __expf(s.w - m), h1, l1);
            *(uint2*)&Ah[r][kc] = make_uint2(h0, h1);
            *(uint2*)&Al[r][kc] = make_uint2(l0, l1);
        }
#pragma unroll
        for (int i = 0; i < 4; i++) {
            int t4 = tid + i * 256;
            int k  = t4 >> 4;
            int dc = (t4 & 15) * 4;
            *(float4*)&Vs[k][dc] = *(const float4*)(Vb + (size_t)(kt + k) * D_ + dc);
        }
        __syncthreads();

#pragma unroll
        for (int k0 = 0; k0 < 64; k0 += 16) {
            u32 ah[2][4], al[2][4], bh[2][2], bl[2][2];
#pragma unroll
            for (int mi = 0; mi < 2; mi++) {
                const __nv_bfloat16* ph = &Ah[wm + mi * 16 + g][k0 + 2 * tg];
                ah[mi][0] = *(const u32*)(ph);
                ah[mi][1] = *(const u32*)(ph + 8 * STRD);
                ah[mi][2] = *(const u32*)(ph + 8);
                ah[mi][3] = *(const u32*)(ph + 8 * STRD + 8);
                const __nv_bfloat16* pl = &Al[wm + mi * 16 + g][k0 + 2 * tg];
                al[mi][0] = *(const u32*)(pl);
                al[mi][1] = *(const u32*)(pl + 8 * STRD);
                al[mi][2] = *(const u32*)(pl + 8);
                al[mi][3] = *(const u32*)(pl + 8 * STRD + 8);
            }
#pragma unroll
            for (int ni = 0; ni < 2; ni++) {
                const int n = wn + ni * 8 + g;
                const int kb = k0 + 2 * tg;
                split2(Vs[kb][n],     Vs[kb + 1][n], bh[ni][0], bl[ni][0]);
                split2(Vs[kb + 8][n], Vs[kb + 9][n], bh[ni][1], bl[ni][1]);
            }
#pragma unroll
            for (int mi = 0; mi < 2; mi++)
#pragma unroll
                for (int ni = 0; ni < 2; ni++) {
                    mma_bf16(c[mi][ni], ah[mi][0], ah[mi][1], ah[mi][2], ah[mi][3],
                             bh[ni][0], bh[ni][1]);
                    mma_bf16(c[mi][ni], al[mi][0], al[mi][1], al[mi][2], al[mi][3],
                             bh[ni][0], bh[ni][1]);
                    mma_bf16(c[mi][ni], ah[mi][0], ah[mi][1], ah[mi][2], ah[mi][3],
                             bl[ni][0], bl[ni][1]);
                }
        }
        __syncthreads();
    }

#pragma unroll
    for (int mi = 0; mi < 2; mi++)
#pragma unroll
        for (int ni = 0; ni < 2; ni++) {
            int m = wm + mi * 16 + g;
            int n = wn + ni * 8 + 2 * tg;
            float inv0 = invs[m], inv1 = invs[m + 8];
            float* d0 = Out + ((size_t)bz * TQ_ + qt + m) * D_ + n;
            *(float2*)d0 = make_float2(c[mi][ni][0] * inv0, c[mi][ni][1] * inv0);
            float* d1 = Out + ((size_t)bz * TQ_ + qt + m + 8) * D_ + n;
            *(float2*)d1 = make_float2(c[mi][ni][2] * inv1, c[mi][ni][3] * inv1);
        }
}

// ---------------------------------------------------------------------------
// Kernel D2: O += (1/sum)*exp(S-m)·pos_v[q]. grid (1024). pos_v fp32 smem.
// ---------------------------------------------------------------------------
extern "C" __global__ void __launch_bounds__(256)
posv_kernel(const float* __restrict__ PV, float* __restrict__ Out)
{
    const int q = blockIdx.x;

    __shared__ __nv_bfloat16 Ah[32][STRD], Al[32][STRD];  // exp'd P
    __shared__ float PVs[64][68];                         // pos_v chunk fp32 [k][d]
    __shared__ float mxs[B_], invs[B_];

    const int tid = threadIdx.x;
    if (tid < B_) {
        mxs[tid]  = g_mx[tid * TQ_ + q];
        invs[tid] = g_inv[tid * TQ_ + q];
    }
    __syncthreads();

    const int wid = tid >> 5, lane = tid & 31;
    const int g = lane >> 2, tg = lane & 3;
    const int wn = wid * 8;

    float c[2][4] = {};

    for (int kt = 0; kt < TK_; kt += 64) {
#pragma unroll
        for (int i = 0; i < 2; i++) {
            int t4 = tid + i * 256;
            int bb = t4 >> 4;
            int kc = (t4 & 15) * 4;
            float4 s = *(const float4*)(g_S + ((size_t)bb * TQ_ + q) * TK_ + kt + kc);
            float m = mxs[bb];
            u32 h0, l0, h1, l1;
            split2(__expf(s.x - m), __expf(s.y - m), h0, l0);
            split2(__expf(s.z - m), __expf(s.w - m), h1, l1);
            *(uint2*)&Ah[bb][kc] = make_uint2(h0, h1);
            *(uint2*)&Al[bb][kc] = make_uint2(l0, l1);
        }
        const float* PVq = PV + ((size_t)q * TK_ + kt) * D_;
#pragma unroll
        for (int i = 0; i < 4; i++) {
            int t4 = tid + i * 256;
            int k  = t4 >> 4;
            int dc = (t4 & 15) * 4;
            *(float4*)&PVs[k][dc] = *(const float4*)(PVq + (size_t)k * D_ + dc);
        }
        __syncthreads();

#pragma unroll
        for (int k0 = 0; k0 < 64; k0 += 16) {
            u32 ah[2][4], al[2][4], bh[2], bl[2];
#pragma unroll
            for (int mi = 0; mi < 2; mi++) {
                const __nv_bfloat16* ph = &Ah[mi * 16 + g][k0 + 2 * tg];
                ah[mi][0] = *(const u32*)(ph);
                ah[mi][1] = *(const u32*)(ph + 8 * STRD);
                ah[mi][2] = *(const u32*)(ph + 8);
                ah[mi][3] = *(const u32*)(ph + 8 * STRD + 8);
                const __nv_bfloat16* pl = &Al[mi * 16 + g][k0 + 2 * tg];
                al[mi][0] = *(const u32*)(pl);
                al[mi][1] = *(const u32*)(pl + 8 * STRD);
                al[mi][2] = *(const u32*)(pl + 8);
                al[mi][3] = *(const u32*)(pl + 8 * STRD + 8);
            }
            {
                const int n = wn + g;
                const int kb = k0 + 2 * tg;
                split2(PVs[kb][n],     PVs[kb + 1][n], bh[0], bl[0]);
                split2(PVs[kb + 8][n], PVs[kb + 9][n], bh[1], bl[1]);
            }
#pragma unroll
            for (int mi = 0; mi < 2; mi++) {
                mma_bf16(c[mi], ah[mi][0], ah[mi][1], ah[mi][2], ah[mi][3], bh[0], bh[1]);
                mma_bf16(c[mi], al[mi][0], al[mi][1], al[mi][2], al[mi][3], bh[0], bh[1]);
                mma_bf16(c[mi], ah[mi][0], ah[mi][1], ah[mi][2], ah[mi][3], bl[0], bl[1]);
            }
        }
        __syncthreads();
    }

#pragma unroll
    for (int mi = 0; mi < 2; mi++) {
        const int b0 = mi * 16 + g;
        const int b1 = b0 + 8;
        const int n  = wn + 2 * tg;
        float* d0 = Out + ((size_t)b0 * TQ_ + q) * D_ + n;
        float2 o0 = *(float2*)d0;
        o0.x += c[mi][0] * invs[b0];
        o0.y += c[mi][1] * invs[b0];
        *(float2*)d0 = o0;
        float* d1 = Out + ((size_t)b1 * TQ_ + q) * D_ + n;
        float2 o1 = *(float2*)d1;
        o1.x += c[mi][2] * invs[b1];
        o1.y += c[mi][3] * invs[b1];
        *(float2*)d1 = o1;
    }
}

// ---------------------------------------------------------------------------
extern "C" void kernel_launch(void* const* d_in, const int* in_sizes, int n_in,
                              void* d_out, int out_size)
{
    const float* Q  = (const float*)d_in[0];
    const float* K  = (const float*)d_in[1];
    const float* V  = (const float*)d_in[2];
    const float* PK = (const float*)d_in[3];
    const float* PV = (const float*)d_in[4];
    const int*   VL = (const int*)d_in[5];
    float* Out = (float*)d_out;

    qk_kernel<<<dim3(TK_ / 64, TQ_ / 64, B_), 256>>>(Q, K);
    posk_kernel<<<dim3(TK_ / 128, TQ_), 256>>>(Q, PK, VL);
    stats_kernel<<<dim3(TQ_, B_), 256>>>();
    pv_kernel<<<dim3(TQ_ / 64, B_), 256>>>(V, Out);
    posv_kernel<<<TQ_, 256>>>(PV, Out);
}

// round 5
// speedup vs baseline: 3.6223x; 1.1455x over previous
#include <cuda_runtime.h>
#include <cuda_bf16.h>
#include <math.h>

typedef unsigned u32;

#define B_  32
#define TQ_ 1024
#define TK_ 1024
#define D_  64
#define STRD 72   // bf16 smem row stride (64 data + 8 pad): conflict-free frag LDS

// scores/probs scratch (134 MB) + per-(b,q) 8-block partial rowsums (1 MB)
static __device__ float g_S[(size_t)B_ * TQ_ * TK_];
static __device__ float g_psum[(size_t)B_ * TQ_ * 8];

// ---- bf16 mma + packed split helpers --------------------------------------
__device__ __forceinline__ void mma_bf16(float c[4], u32 a0, u32 a1, u32 a2, u32 a3,
                                         u32 b0, u32 b1)
{
    asm volatile(
        "mma.sync.aligned.m16n8k16.row.col.f32.bf16.bf16.f32 "
        "{%0,%1,%2,%3},{%4,%5,%6,%7},{%8,%9},{%0,%1,%2,%3};\n"
        : "+f"(c[0]), "+f"(c[1]), "+f"(c[2]), "+f"(c[3])
        : "r"(a0), "r"(a1), "r"(a2), "r"(a3), "r"(b0), "r"(b1));
}

__device__ __forceinline__ u32 cvt2(float hi, float lo) {
    u32 r;
    asm("cvt.rn.bf16x2.f32 %0,%1,%2;" : "=r"(r) : "f"(hi), "f"(lo));
    return r;
}
// x0 -> low bf16, x1 -> high bf16; h = packed hi parts, l = packed residuals
__device__ __forceinline__ void split2(float x0, float x1, u32& h, u32& l) {
    h = cvt2(x1, x0);
    float h0 = __uint_as_float(h << 16);          // exact bf16->f32
    float h1 = __uint_as_float(h & 0xffff0000u);
    l = cvt2(x1 - h1, x0 - h0);
}

// ---------------------------------------------------------------------------
// Kernel A: S[b,q,k] = Q[b,q,:]·K[b,k,:] (unscaled). grid (16,16,32), 256 thr.
// ---------------------------------------------------------------------------
extern "C" __global__ void __launch_bounds__(256)
qk_kernel(const float* __restrict__ Q, const float* __restrict__ K)
{
    const int bz = blockIdx.z;
    const int qt = blockIdx.y * 64;
    const int kt = blockIdx.x * 64;
    const float* Qb = Q + (size_t)bz * TQ_ * D_;
    const float* Kb = K + (size_t)bz * TK_ * D_;
    float* Sb = g_S + (size_t)bz * TQ_ * TK_;

    __shared__ __nv_bfloat16 Ah[64][STRD], Al[64][STRD];
    __shared__ __nv_bfloat16 Bh[64][STRD], Bl[64][STRD];

    const int tid = threadIdx.x;
#pragma unroll
    for (int i = 0; i < 4; i++) {
        int t4  = tid + i * 256;
        int row = t4 >> 4;
        int col = (t4 & 15) * 4;
        float4 v = *(const float4*)(Qb + (size_t)(qt + row) * D_ + col);
        u32 h0, l0, h1, l1;
        split2(v.x, v.y, h0, l0); split2(v.z, v.w, h1, l1);
        *(uint2*)&Ah[row][col] = make_uint2(h0, h1);
        *(uint2*)&Al[row][col] = make_uint2(l0, l1);
        float4 w = *(const float4*)(Kb + (size_t)(kt + row) * D_ + col);
        split2(w.x, w.y, h0, l0); split2(w.z, w.w, h1, l1);
        *(uint2*)&Bh[row][col] = make_uint2(h0, h1);
        *(uint2*)&Bl[row][col] = make_uint2(l0, l1);
    }
    __syncthreads();

    const int wid = tid >> 5, lane = tid & 31;
    const int g = lane >> 2, tg = lane & 3;
    const int wm = (wid >> 2) * 32;
    const int wn = (wid & 3) * 16;

    float c[2][2][4] = {};

#pragma unroll
    for (int k0 = 0; k0 < 64; k0 += 16) {
        u32 ah[2][4], al[2][4], bh[2][2], bl[2][2];
#pragma unroll
        for (int mi = 0; mi < 2; mi++) {
            const __nv_bfloat16* ph = &Ah[wm + mi * 16 + g][k0 + 2 * tg];
            ah[mi][0] = *(const u32*)(ph);
            ah[mi][1] = *(const u32*)(ph + 8 * STRD);
            ah[mi][2] = *(const u32*)(ph + 8);
            ah[mi][3] = *(const u32*)(ph + 8 * STRD + 8);
            const __nv_bfloat16* pl = &Al[wm + mi * 16 + g][k0 + 2 * tg];
            al[mi][0] = *(const u32*)(pl);
            al[mi][1] = *(const u32*)(pl + 8 * STRD);
            al[mi][2] = *(const u32*)(pl + 8);
            al[mi][3] = *(const u32*)(pl + 8 * STRD + 8);
        }
#pragma unroll
        for (int ni = 0; ni < 2; ni++) {
            const __nv_bfloat16* ph = &Bh[wn + ni * 8 + g][k0 + 2 * tg];
            bh[ni][0] = *(const u32*)(ph);
            bh[ni][1] = *(const u32*)(ph + 8);
            const __nv_bfloat16* pl = &Bl[wn + ni * 8 + g][k0 + 2 * tg];
            bl[ni][0] = *(const u32*)(pl);
            bl[ni][1] = *(const u32*)(pl + 8);
        }
#pragma unroll
        for (int mi = 0; mi < 2; mi++)
#pragma unroll
            for (int ni = 0; ni < 2; ni++) {
                mma_bf16(c[mi][ni], ah[mi][0], ah[mi][1], ah[mi][2], ah[mi][3],
                         bh[ni][0], bh[ni][1]);
                mma_bf16(c[mi][ni], al[mi][0], al[mi][1], al[mi][2], al[mi][3],
                         bh[ni][0], bh[ni][1]);
                mma_bf16(c[mi][ni], ah[mi][0], ah[mi][1], ah[mi][2], ah[mi][3],
                         bl[ni][0], bl[ni][1]);
            }
    }

#pragma unroll
    for (int mi = 0; mi < 2; mi++)
#pragma unroll
        for (int ni = 0; ni < 2; ni++) {
            int m = qt + wm + mi * 16 + g;
            int n = kt + wn + ni * 8 + 2 * tg;
            *(float2*)&Sb[(size_t)m * TK_ + n] =
                make_float2(c[mi][ni][0], c[mi][ni][1]);
            *(float2*)&Sb[(size_t)(m + 8) * TK_ + n] =
                make_float2(c[mi][ni][2], c[mi][ni][3]);
        }
}

// ---------------------------------------------------------------------------
// Kernel B: P = exp(mask((S + Q·pos_k)/8)) in place; emits partial rowsums.
// grid (8, 1024), 256 thr. pos_k read exactly once. No max needed: |s|<~12.
// ---------------------------------------------------------------------------
extern "C" __global__ void __launch_bounds__(256)
posk_kernel(const float* __restrict__ Q, const float* __restrict__ PK,
            const int* __restrict__ VL)
{
    const int q  = blockIdx.y;
    const int kt = blockIdx.x * 128;

    __shared__ __nv_bfloat16 Ah[32][STRD], Al[32][STRD];
    __shared__ __nv_bfloat16 Bh[128][STRD], Bl[128][STRD];
    __shared__ float rsum[32][8];
    __shared__ int vls[B_];

    const int tid = threadIdx.x;
#pragma unroll
    for (int i = 0; i < 2; i++) {
        int t4  = tid + i * 256;
        int row = t4 >> 4;
        int col = (t4 & 15) * 4;
        float4 v = *(const float4*)(Q + ((size_t)row * TQ_ + q) * D_ + col);
        u32 h0, l0, h1, l1;
        split2(v.x, v.y, h0, l0); split2(v.z, v.w, h1, l1);
        *(uint2*)&Ah[row][col] = make_uint2(h0, h1);
        *(uint2*)&Al[row][col] = make_uint2(l0, l1);
    }
    const float* PKq = PK + ((size_t)q * TK_ + kt) * D_;
#pragma unroll
    for (int i = 0; i < 8; i++) {
        int t4  = tid + i * 256;
        int row = t4 >> 4;
        int col = (t4 & 15) * 4;
        float4 v = *(const float4*)(PKq + (size_t)row * D_ + col);
        u32 h0, l0, h1, l1;
        split2(v.x, v.y, h0, l0); split2(v.z, v.w, h1, l1);
        *(uint2*)&Bh[row][col] = make_uint2(h0, h1);
        *(uint2*)&Bl[row][col] = make_uint2(l0, l1);
    }
    if (tid < B_) vls[tid] = VL[tid];
    __syncthreads();

    const int wid = tid >> 5, lane = tid & 31;
    const int g = lane >> 2, tg = lane & 3;
    const int wn = wid * 16;

    float c[2][2][4] = {};

#pragma unroll
    for (int k0 = 0; k0 < 64; k0 += 16) {
        u32 ah[2][4], al[2][4], bh[2][2], bl[2][2];
#pragma unroll
        for (int mi = 0; mi < 2; mi++) {
            const __nv_bfloat16* ph = &Ah[mi * 16 + g][k0 + 2 * tg];
            ah[mi][0] = *(const u32*)(ph);
            ah[mi][1] = *(const u32*)(ph + 8 * STRD);
            ah[mi][2] = *(const u32*)(ph + 8);
            ah[mi][3] = *(const u32*)(ph + 8 * STRD + 8);
            const __nv_bfloat16* pl = &Al[mi * 16 + g][k0 + 2 * tg];
            al[mi][0] = *(const u32*)(pl);
            al[mi][1] = *(const u32*)(pl + 8 * STRD);
            al[mi][2] = *(const u32*)(pl + 8);
            al[mi][3] = *(const u32*)(pl + 8 * STRD + 8);
        }
#pragma unroll
        for (int ni = 0; ni < 2; ni++) {
            const __nv_bfloat16* ph = &Bh[wn + ni * 8 + g][k0 + 2 * tg];
            bh[ni][0] = *(const u32*)(ph);
            bh[ni][1] = *(const u32*)(ph + 8);
            const __nv_bfloat16* pl = &Bl[wn + ni * 8 + g][k0 + 2 * tg];
            bl[ni][0] = *(const u32*)(pl);
            bl[ni][1] = *(const u32*)(pl + 8);
        }
#pragma unroll
        for (int mi = 0; mi < 2; mi++)
#pragma unroll
            for (int ni = 0; ni < 2; ni++) {
                mma_bf16(c[mi][ni], ah[mi][0], ah[mi][1], ah[mi][2], ah[mi][3],
                         bh[ni][0], bh[ni][1]);
                mma_bf16(c[mi][ni], al[mi][0], al[mi][1], al[mi][2], al[mi][3],
                         bh[ni][0], bh[ni][1]);
                mma_bf16(c[mi][ni], ah[mi][0], ah[mi][1], ah[mi][2], ah[mi][3],
                         bl[ni][0], bl[ni][1]);
            }
    }

    // epilogue: P = exp(masked (S + c)/8), write back, accumulate row sums
    float rs[2][2] = {};
#pragma unroll
    for (int mi = 0; mi < 2; mi++) {
        const int b0  = mi * 16 + g;
        const int b1  = b0 + 8;
        const int vl0 = vls[b0];
        const int vl1 = vls[b1];
#pragma unroll
        for (int ni = 0; ni < 2; ni++) {
            const int col = kt + wn + ni * 8 + 2 * tg;
            float* p0 = &g_S[((size_t)b0 * TQ_ + q) * TK_ + col];
            float2 s0 = *(float2*)p0;
            s0.x = (col     < vl0) ? __expf((s0.x + c[mi][ni][0]) * 0.125f) : 0.f;
            s0.y = (col + 1 < vl0) ? __expf((s0.y + c[mi][ni][1]) * 0.125f) : 0.f;
            *(float2*)p0 = s0;
            rs[mi][0] += s0.x + s0.y;
            float* p1 = &g_S[((size_t)b1 * TQ_ + q) * TK_ + col];
            float2 s1 = *(float2*)p1;
            s1.x = (col     < vl1) ? __expf((s1.x + c[mi][ni][2]) * 0.125f) : 0.f;
            s1.y = (col + 1 < vl1) ? __expf((s1.y + c[mi][ni][3]) * 0.125f) : 0.f;
            *(float2*)p1 = s1;
            rs[mi][1] += s1.x + s1.y;
        }
    }
    // reduce over tg (4 lanes, fixed order)
#pragma unroll
    for (int mi = 0; mi < 2; mi++)
#pragma unroll
        for (int r = 0; r < 2; r++) {
            rs[mi][r] += __shfl_xor_sync(0xffffffffu, rs[mi][r], 1);
            rs[mi][r] += __shfl_xor_sync(0xffffffffu, rs[mi][r], 2);
        }
    if (tg == 0) {
#pragma unroll
        for (int mi = 0; mi < 2; mi++) {
            rsum[mi * 16 + g][wid]     = rs[mi][0];
            rsum[mi * 16 + g + 8][wid] = rs[mi][1];
        }
    }
    __syncthreads();
    if (tid < 32) {
        float4 a = *(float4*)&rsum[tid][0];
        float4 b = *(float4*)&rsum[tid][4];
        g_psum[((size_t)tid * TQ_ + q) * 8 + blockIdx.x] =
            ((a.x + a.y) + (a.z + a.w)) + ((b.x + b.y) + (b.z + b.w));
    }
}

// ---------------------------------------------------------------------------
// Kernel C: O = (1/sum) * P · V. grid (16,32), 256 thr. Pure GEMM over P.
// ---------------------------------------------------------------------------
extern "C" __global__ void __launch_bounds__(256)
pv_kernel(const float* __restrict__ V, float* __restrict__ Out)
{
    const int bz = blockIdx.y;
    const int qt = blockIdx.x * 64;
    const float* Vb = V + (size_t)bz * TK_ * D_;
    const float* Sb = g_S + (size_t)bz * TQ_ * TK_;

    __shared__ __nv_bfloat16 Ah[64][STRD], Al[64][STRD];  // P chunk
    __shared__ float Vs[64][68];                          // V chunk fp32 [k][d]
    __shared__ float invs[64];

    const int tid = threadIdx.x;
    if (tid < 64) {
        const float* ps = &g_psum[((size_t)bz * TQ_ + qt + tid) * 8];
        float4 a = *(const float4*)ps;
        float4 b = *(const float4*)(ps + 4);
        invs[tid] = 1.0f / (((a.x + a.y) + (a.z + a.w)) + ((b.x + b.y) + (b.z + b.w)));
    }
    __syncthreads();

    const int wid = tid >> 5, lane = tid & 31;
    const int g = lane >> 2, tg = lane & 3;
    const int wm = (wid >> 2) * 32;
    const int wn = (wid & 3) * 16;

    float c[2][2][4] = {};

    for (int kt = 0; kt < TK_; kt += 64) {
#pragma unroll
        for (int i = 0; i < 4; i++) {
            int t4 = tid + i * 256;
            int r  = t4 >> 4;
            int kc = (t4 & 15) * 4;
            float4 p = *(const float4*)(Sb + (size_t)(qt + r) * TK_ + kt + kc);
            u32 h0, l0, h1, l1;
            split2(p.x, p.y, h0, l0);
            split2(p.z, p.w, h1, l1);
            *(uint2*)&Ah[r][kc] = make_uint2(h0, h1);
            *(uint2*)&Al[r][kc] = make_uint2(l0, l1);
        }
#pragma unroll
        for (int i = 0; i < 4; i++) {
            int t4 = tid + i * 256;
            int k  = t4 >> 4;
            int dc = (t4 & 15) * 4;
            *(float4*)&Vs[k][dc] = *(const float4*)(Vb + (size_t)(kt + k) * D_ + dc);
        }
        __syncthreads();

#pragma unroll
        for (int k0 = 0; k0 < 64; k0 += 16) {
            u32 ah[2][4], al[2][4], bh[2][2], bl[2][2];
#pragma unroll
            for (int mi = 0; mi < 2; mi++) {
                const __nv_bfloat16* ph = &Ah[wm + mi * 16 + g][k0 + 2 * tg];
                ah[mi][0] = *(const u32*)(ph);
                ah[mi][1] = *(const u32*)(ph + 8 * STRD);
                ah[mi][2] = *(const u32*)(ph + 8);
                ah[mi][3] = *(const u32*)(ph + 8 * STRD + 8);
                const __nv_bfloat16* pl = &Al[wm + mi * 16 + g][k0 + 2 * tg];
                al[mi][0] = *(const u32*)(pl);
                al[mi][1] = *(const u32*)(pl + 8 * STRD);
                al[mi][2] = *(const u32*)(pl + 8);
                al[mi][3] = *(const u32*)(pl + 8 * STRD + 8);
            }
#pragma unroll
            for (int ni = 0; ni < 2; ni++) {
                const int n = wn + ni * 8 + g;
                const int kb = k0 + 2 * tg;
                split2(Vs[kb][n],     Vs[kb + 1][n], bh[ni][0], bl[ni][0]);
                split2(Vs[kb + 8][n], Vs[kb + 9][n], bh[ni][1], bl[ni][1]);
            }
#pragma unroll
            for (int mi = 0; mi < 2; mi++)
#pragma unroll
                for (int ni = 0; ni < 2; ni++) {
                    mma_bf16(c[mi][ni], ah[mi][0], ah[mi][1], ah[mi][2], ah[mi][3],
                             bh[ni][0], bh[ni][1]);
                    mma_bf16(c[mi][ni], al[mi][0], al[mi][1], al[mi][2], al[mi][3],
                             bh[ni][0], bh[ni][1]);
                    mma_bf16(c[mi][ni], ah[mi][0], ah[mi][1], ah[mi][2], ah[mi][3],
                             bl[ni][0], bl[ni][1]);
                }
        }
        __syncthreads();
    }

#pragma unroll
    for (int mi = 0; mi < 2; mi++)
#pragma unroll
        for (int ni = 0; ni < 2; ni++) {
            int m = wm + mi * 16 + g;
            int n = wn + ni * 8 + 2 * tg;
            float inv0 = invs[m], inv1 = invs[m + 8];
            float* d0 = Out + ((size_t)bz * TQ_ + qt + m) * D_ + n;
            *(float2*)d0 = make_float2(c[mi][ni][0] * inv0, c[mi][ni][1] * inv0);
            float* d1 = Out + ((size_t)bz * TQ_ + qt + m + 8) * D_ + n;
            *(float2*)d1 = make_float2(c[mi][ni][2] * inv1, c[mi][ni][3] * inv1);
        }
}

// ---------------------------------------------------------------------------
// Kernel D: O += (1/sum) * P · pos_v[q]. grid (1024). Pure GEMM over P.
// ---------------------------------------------------------------------------
extern "C" __global__ void __launch_bounds__(256)
posv_kernel(const float* __restrict__ PV, float* __restrict__ Out)
{
    const int q = blockIdx.x;

    __shared__ __nv_bfloat16 Ah[32][STRD], Al[32][STRD];  // P chunk
    __shared__ float PVs[64][68];                         // pos_v chunk fp32 [k][d]
    __shared__ float invs[B_];

    const int tid = threadIdx.x;
    if (tid < B_) {
        const float* ps = &g_psum[((size_t)tid * TQ_ + q) * 8];
        float4 a = *(const float4*)ps;
        float4 b = *(const float4*)(ps + 4);
        invs[tid] = 1.0f / (((a.x + a.y) + (a.z + a.w)) + ((b.x + b.y) + (b.z + b.w)));
    }
    __syncthreads();

    const int wid = tid >> 5, lane = tid & 31;
    const int g = lane >> 2, tg = lane & 3;
    const int wn = wid * 8;

    float c[2][4] = {};

    for (int kt = 0; kt < TK_; kt += 64) {
#pragma unroll
        for (int i = 0; i < 2; i++) {
            int t4 = tid + i * 256;
            int bb = t4 >> 4;
            int kc = (t4 & 15) * 4;
            float4 p = *(const float4*)(g_S + ((size_t)bb * TQ_ + q) * TK_ + kt + kc);
            u32 h0, l0, h1, l1;
            split2(p.x, p.y, h0, l0);
            split2(p.z, p.w, h1, l1);
            *(uint2*)&Ah[bb][kc] = make_uint2(h0, h1);
            *(uint2*)&Al[bb][kc] = make_uint2(l0, l1);
        }
        const float* PVq = PV + ((size_t)q * TK_ + kt) * D_;
#pragma unroll
        for (int i = 0; i < 4; i++) {
            int t4 = tid + i * 256;
            int k  = t4 >> 4;
            int dc = (t4 & 15) * 4;
            *(float4*)&PVs[k][dc] = *(const float4*)(PVq + (size_t)k * D_ + dc);
        }
        __syncthreads();

#pragma unroll
        for (int k0 = 0; k0 < 64; k0 += 16) {
            u32 ah[2][4], al[2][4], bh[2], bl[2];
#pragma unroll
            for (int mi = 0; mi < 2; mi++) {
                const __nv_bfloat16* ph = &Ah[mi * 16 + g][k0 + 2 * tg];
                ah[mi][0] = *(const u32*)(ph);
                ah[mi][1] = *(const u32*)(ph + 8 * STRD);
                ah[mi][2] = *(const u32*)(ph + 8);
                ah[mi][3] = *(const u32*)(ph + 8 * STRD + 8);
                const __nv_bfloat16* pl = &Al[mi * 16 + g][k0 + 2 * tg];
                al[mi][0] = *(const u32*)(pl);
                al[mi][1] = *(const u32*)(pl + 8 * STRD);
                al[mi][2] = *(const u32*)(pl + 8);
                al[mi][3] = *(const u32*)(pl + 8 * STRD + 8);
            }
            {
                const int n = wn + g;
                const int kb = k0 + 2 * tg;
                split2(PVs[kb][n],     PVs[kb + 1][n], bh[0], bl[0]);
                split2(PVs[kb + 8][n], PVs[kb + 9][n], bh[1], bl[1]);
            }
#pragma unroll
            for (int mi = 0; mi < 2; mi++) {
                mma_bf16(c[mi], ah[mi][0], ah[mi][1], ah[mi][2], ah[mi][3], bh[0], bh[1]);
                mma_bf16(c[mi], al[mi][0], al[mi][1], al[mi][2], al[mi][3], bh[0], bh[1]);
                mma_bf16(c[mi], ah[mi][0], ah[mi][1], ah[mi][2], ah[mi][3], bl[0], bl[1]);
            }
        }
        __syncthreads();
    }

#pragma unroll
    for (int mi = 0; mi < 2; mi++) {
        const int b0 = mi * 16 + g;
        const int b1 = b0 + 8;
        const int n  = wn + 2 * tg;
        float* d0 = Out + ((size_t)b0 * TQ_ + q) * D_ + n;
        float2 o0 = *(float2*)d0;
        o0.x += c[mi][0] * invs[b0];
        o0.y += c[mi][1] * invs[b0];
        *(float2*)d0 = o0;
        float* d1 = Out + ((size_t)b1 * TQ_ + q) * D_ + n;
        float2 o1 = *(float2*)d1;
        o1.x += c[mi][2] * invs[b1];
        o1.y += c[mi][3] * invs[b1];
        *(float2*)d1 = o1;
    }
}

// ---------------------------------------------------------------------------
extern "C" void kernel_launch(void* const* d_in, const int* in_sizes, int n_in,
                              void* d_out, int out_size)
{
    const float* Q  = (const float*)d_in[0];
    const float* K  = (const float*)d_in[1];
    const float* V  = (const float*)d_in[2];
    const float* PK = (const float*)d_in[3];
    const float* PV = (const float*)d_in[4];
    const int*   VL = (const int*)d_in[5];
    float* Out = (float*)d_out;

    qk_kernel<<<dim3(TK_ / 64, TQ_ / 64, B_), 256>>>(Q, K);
    posk_kernel<<<dim3(TK_ / 128, TQ_), 256>>>(Q, PK, VL);
    pv_kernel<<<dim3(TQ_ / 64, B_), 256>>>(V, Out);
    posv_kernel<<<TQ_, 256>>>(PV, Out);
}

// round 6
// speedup vs baseline: 3.9003x; 1.0767x over previous
#include <cuda_runtime.h>
#include <cuda_bf16.h>
#include <cuda_fp16.h>
#include <math.h>

typedef unsigned u32;

#define B_  32
#define TQ_ 1024
#define TK_ 1024
#define D_  64
#define STRD 72   // smem row stride in 2B elems (64 data + 8 pad): conflict-free frags

// scratch: fp32 scores, fp16 probs, per-(b,q) 8-block partial rowsums
static __device__ float  g_S[(size_t)B_ * TQ_ * TK_];
static __device__ __half g_P[(size_t)B_ * TQ_ * TK_];
static __device__ float  g_psum[(size_t)B_ * TQ_ * 8];

// ---- mma helpers ----------------------------------------------------------
__device__ __forceinline__ void mma_bf16(float c[4], u32 a0, u32 a1, u32 a2, u32 a3,
                                         u32 b0, u32 b1)
{
    asm volatile(
        "mma.sync.aligned.m16n8k16.row.col.f32.bf16.bf16.f32 "
        "{%0,%1,%2,%3},{%4,%5,%6,%7},{%8,%9},{%0,%1,%2,%3};\n"
        : "+f"(c[0]), "+f"(c[1]), "+f"(c[2]), "+f"(c[3])
        : "r"(a0), "r"(a1), "r"(a2), "r"(a3), "r"(b0), "r"(b1));
}
__device__ __forceinline__ void mma_f16(float c[4], u32 a0, u32 a1, u32 a2, u32 a3,
                                        u32 b0, u32 b1)
{
    asm volatile(
        "mma.sync.aligned.m16n8k16.row.col.f32.f16.f16.f32 "
        "{%0,%1,%2,%3},{%4,%5,%6,%7},{%8,%9},{%0,%1,%2,%3};\n"
        : "+f"(c[0]), "+f"(c[1]), "+f"(c[2]), "+f"(c[3])
        : "r"(a0), "r"(a1), "r"(a2), "r"(a3), "r"(b0), "r"(b1));
}

__device__ __forceinline__ u32 cvt2bf(float hi, float lo) {
    u32 r;
    asm("cvt.rn.bf16x2.f32 %0,%1,%2;" : "=r"(r) : "f"(hi), "f"(lo));
    return r;
}
// bf16 hi/lo split (x0 -> low half, x1 -> high half)
__device__ __forceinline__ void split2(float x0, float x1, u32& h, u32& l) {
    h = cvt2bf(x1, x0);
    float h0 = __uint_as_float(h << 16);
    float h1 = __uint_as_float(h & 0xffff0000u);
    l = cvt2bf(x1 - h1, x0 - h0);
}
// fp16 hi/lo split
__device__ __forceinline__ void split2h(float x0, float x1, u32& h, u32& l) {
    __half2 hh = __floats2half2_rn(x0, x1);
    h = *(u32*)&hh;
    float2 hf = __half22float2(hh);
    __half2 ll = __floats2half2_rn(x0 - hf.x, x1 - hf.y);
    l = *(u32*)&ll;
}

// ---------------------------------------------------------------------------
// Kernel A: S[b,q,k] = Q[b,q,:]·K[b,k,:] (unscaled, fp32 out). bf16x3 MMA.
// ---------------------------------------------------------------------------
extern "C" __global__ void __launch_bounds__(256)
qk_kernel(const float* __restrict__ Q, const float* __restrict__ K)
{
    const int bz = blockIdx.z;
    const int qt = blockIdx.y * 64;
    const int kt = blockIdx.x * 64;
    const float* Qb = Q + (size_t)bz * TQ_ * D_;
    const float* Kb = K + (size_t)bz * TK_ * D_;
    float* Sb = g_S + (size_t)bz * TQ_ * TK_;

    __shared__ __nv_bfloat16 Ah[64][STRD], Al[64][STRD];
    __shared__ __nv_bfloat16 Bh[64][STRD], Bl[64][STRD];

    const int tid = threadIdx.x;
#pragma unroll
    for (int i = 0; i < 4; i++) {
        int t4  = tid + i * 256;
        int row = t4 >> 4;
        int col = (t4 & 15) * 4;
        float4 v = *(const float4*)(Qb + (size_t)(qt + row) * D_ + col);
        u32 h0, l0, h1, l1;
        split2(v.x, v.y, h0, l0); split2(v.z, v.w, h1, l1);
        *(uint2*)&Ah[row][col] = make_uint2(h0, h1);
        *(uint2*)&Al[row][col] = make_uint2(l0, l1);
        float4 w = *(const float4*)(Kb + (size_t)(kt + row) * D_ + col);
        split2(w.x, w.y, h0, l0); split2(w.z, w.w, h1, l1);
        *(uint2*)&Bh[row][col] = make_uint2(h0, h1);
        *(uint2*)&Bl[row][col] = make_uint2(l0, l1);
    }
    __syncthreads();

    const int wid = tid >> 5, lane = tid & 31;
    const int g = lane >> 2, tg = lane & 3;
    const int wm = (wid >> 2) * 32;
    const int wn = (wid & 3) * 16;

    float c[2][2][4] = {};

#pragma unroll
    for (int k0 = 0; k0 < 64; k0 += 16) {
        u32 ah[2][4], al[2][4], bh[2][2], bl[2][2];
#pragma unroll
        for (int mi = 0; mi < 2; mi++) {
            const __nv_bfloat16* ph = &Ah[wm + mi * 16 + g][k0 + 2 * tg];
            ah[mi][0] = *(const u32*)(ph);
            ah[mi][1] = *(const u32*)(ph + 8 * STRD);
            ah[mi][2] = *(const u32*)(ph + 8);
            ah[mi][3] = *(const u32*)(ph + 8 * STRD + 8);
            const __nv_bfloat16* pl = &Al[wm + mi * 16 + g][k0 + 2 * tg];
            al[mi][0] = *(const u32*)(pl);
            al[mi][1] = *(const u32*)(pl + 8 * STRD);
            al[mi][2] = *(const u32*)(pl + 8);
            al[mi][3] = *(const u32*)(pl + 8 * STRD + 8);
        }
#pragma unroll
        for (int ni = 0; ni < 2; ni++) {
            const __nv_bfloat16* ph = &Bh[wn + ni * 8 + g][k0 + 2 * tg];
            bh[ni][0] = *(const u32*)(ph);
            bh[ni][1] = *(const u32*)(ph + 8);
            const __nv_bfloat16* pl = &Bl[wn + ni * 8 + g][k0 + 2 * tg];
            bl[ni][0] = *(const u32*)(pl);
            bl[ni][1] = *(const u32*)(pl + 8);
        }
#pragma unroll
        for (int mi = 0; mi < 2; mi++)
#pragma unroll
            for (int ni = 0; ni < 2; ni++) {
                mma_bf16(c[mi][ni], ah[mi][0], ah[mi][1], ah[mi][2], ah[mi][3],
                         bh[ni][0], bh[ni][1]);
                mma_bf16(c[mi][ni], al[mi][0], al[mi][1], al[mi][2], al[mi][3],
                         bh[ni][0], bh[ni][1]);
                mma_bf16(c[mi][ni], ah[mi][0], ah[mi][1], ah[mi][2], ah[mi][3],
                         bl[ni][0], bl[ni][1]);
            }
    }

#pragma unroll
    for (int mi = 0; mi < 2; mi++)
#pragma unroll
        for (int ni = 0; ni < 2; ni++) {
            int m = qt + wm + mi * 16 + g;
            int n = kt + wn + ni * 8 + 2 * tg;
            *(float2*)&Sb[(size_t)m * TK_ + n] =
                make_float2(c[mi][ni][0], c[mi][ni][1]);
            *(float2*)&Sb[(size_t)(m + 8) * TK_ + n] =
                make_float2(c[mi][ni][2], c[mi][ni][3]);
        }
}

// ---------------------------------------------------------------------------
// Kernel B: P(fp16) = exp(mask((S + Q·pos_k)/8)); emits partial rowsums of
// the fp16-ROUNDED values (exactly consistent normalization).
// ---------------------------------------------------------------------------
extern "C" __global__ void __launch_bounds__(256)
posk_kernel(const float* __restrict__ Q, const float* __restrict__ PK,
            const int* __restrict__ VL)
{
    const int q  = blockIdx.y;
    const int kt = blockIdx.x * 128;

    __shared__ __nv_bfloat16 Ah[32][STRD], Al[32][STRD];
    __shared__ __nv_bfloat16 Bh[128][STRD], Bl[128][STRD];
    __shared__ float rsum[32][8];
    __shared__ int vls[B_];

    const int tid = threadIdx.x;
#pragma unroll
    for (int i = 0; i < 2; i++) {
        int t4  = tid + i * 256;
        int row = t4 >> 4;
        int col = (t4 & 15) * 4;
        float4 v = *(const float4*)(Q + ((size_t)row * TQ_ + q) * D_ + col);
        u32 h0, l0, h1, l1;
        split2(v.x, v.y, h0, l0); split2(v.z, v.w, h1, l1);
        *(uint2*)&Ah[row][col] = make_uint2(h0, h1);
        *(uint2*)&Al[row][col] = make_uint2(l0, l1);
    }
    const float* PKq = PK + ((size_t)q * TK_ + kt) * D_;
#pragma unroll
    for (int i = 0; i < 8; i++) {
        int t4  = tid + i * 256;
        int row = t4 >> 4;
        int col = (t4 & 15) * 4;
        float4 v = *(const float4*)(PKq + (size_t)row * D_ + col);
        u32 h0, l0, h1, l1;
        split2(v.x, v.y, h0, l0); split2(v.z, v.w, h1, l1);
        *(uint2*)&Bh[row][col] = make_uint2(h0, h1);
        *(uint2*)&Bl[row][col] = make_uint2(l0, l1);
    }
    if (tid < B_) vls[tid] = VL[tid];
    __syncthreads();

    const int wid = tid >> 5, lane = tid & 31;
    const int g = lane >> 2, tg = lane & 3;
    const int wn = wid * 16;

    float c[2][2][4] = {};

#pragma unroll
    for (int k0 = 0; k0 < 64; k0 += 16) {
        u32 ah[2][4], al[2][4], bh[2][2], bl[2][2];
#pragma unroll
        for (int mi = 0; mi < 2; mi++) {
            const __nv_bfloat16* ph = &Ah[mi * 16 + g][k0 + 2 * tg];
            ah[mi][0] = *(const u32*)(ph);
            ah[mi][1] = *(const u32*)(ph + 8 * STRD);
            ah[mi][2] = *(const u32*)(ph + 8);
            ah[mi][3] = *(const u32*)(ph + 8 * STRD + 8);
            const __nv_bfloat16* pl = &Al[mi * 16 + g][k0 + 2 * tg];
            al[mi][0] = *(const u32*)(pl);
            al[mi][1] = *(const u32*)(pl + 8 * STRD);
            al[mi][2] = *(const u32*)(pl + 8);
            al[mi][3] = *(const u32*)(pl + 8 * STRD + 8);
        }
#pragma unroll
        for (int ni = 0; ni < 2; ni++) {
            const __nv_bfloat16* ph = &Bh[wn + ni * 8 + g][k0 + 2 * tg];
            bh[ni][0] = *(const u32*)(ph);
            bh[ni][1] = *(const u32*)(ph + 8);
            const __nv_bfloat16* pl = &Bl[wn + ni * 8 + g][k0 + 2 * tg];
            bl[ni][0] = *(const u32*)(pl);
            bl[ni][1] = *(const u32*)(pl + 8);
        }
#pragma unroll
        for (int mi = 0; mi < 2; mi++)
#pragma unroll
            for (int ni = 0; ni < 2; ni++) {
                mma_bf16(c[mi][ni], ah[mi][0], ah[mi][1], ah[mi][2], ah[mi][3],
                         bh[ni][0], bh[ni][1]);
                mma_bf16(c[mi][ni], al[mi][0], al[mi][1], al[mi][2], al[mi][3],
                         bh[ni][0], bh[ni][1]);
                mma_bf16(c[mi][ni], ah[mi][0], ah[mi][1], ah[mi][2], ah[mi][3],
                         bl[ni][0], bl[ni][1]);
            }
    }

    // epilogue: read S, add, mask, exp, round to fp16, store P, sum rounded
    float rs[2][2] = {};
#pragma unroll
    for (int mi = 0; mi < 2; mi++) {
        const int b0  = mi * 16 + g;
        const int b1  = b0 + 8;
        const int vl0 = vls[b0];
        const int vl1 = vls[b1];
#pragma unroll
        for (int ni = 0; ni < 2; ni++) {
            const int col = kt + wn + ni * 8 + 2 * tg;
            {
                float2 s0 = *(const float2*)&g_S[((size_t)b0 * TQ_ + q) * TK_ + col];
                float e0 = (col     < vl0) ? __expf((s0.x + c[mi][ni][0]) * 0.125f) : 0.f;
                float e1 = (col + 1 < vl0) ? __expf((s0.y + c[mi][ni][1]) * 0.125f) : 0.f;
                __half2 hp = __floats2half2_rn(e0, e1);
                *(__half2*)&g_P[((size_t)b0 * TQ_ + q) * TK_ + col] = hp;
                float2 er = __half22float2(hp);
                rs[mi][0] += er.x + er.y;
            }
            {
                float2 s1 = *(const float2*)&g_S[((size_t)b1 * TQ_ + q) * TK_ + col];
                float e0 = (col     < vl1) ? __expf((s1.x + c[mi][ni][2]) * 0.125f) : 0.f;
                float e1 = (col + 1 < vl1) ? __expf((s1.y + c[mi][ni][3]) * 0.125f) : 0.f;
                __half2 hp = __floats2half2_rn(e0, e1);
                *(__half2*)&g_P[((size_t)b1 * TQ_ + q) * TK_ + col] = hp;
                float2 er = __half22float2(hp);
                rs[mi][1] += er.x + er.y;
            }
        }
    }
#pragma unroll
    for (int mi = 0; mi < 2; mi++)
#pragma unroll
        for (int r = 0; r < 2; r++) {
            rs[mi][r] += __shfl_xor_sync(0xffffffffu, rs[mi][r], 1);
            rs[mi][r] += __shfl_xor_sync(0xffffffffu, rs[mi][r], 2);
        }
    if (tg == 0) {
#pragma unroll
        for (int mi = 0; mi < 2; mi++) {
            rsum[mi * 16 + g][wid]     = rs[mi][0];
            rsum[mi * 16 + g + 8][wid] = rs[mi][1];
        }
    }
    __syncthreads();
    if (tid < 32) {
        float4 a = *(float4*)&rsum[tid][0];
        float4 b = *(float4*)&rsum[tid][4];
        g_psum[((size_t)tid * TQ_ + q) * 8 + blockIdx.x] =
            ((a.x + a.y) + (a.z + a.w)) + ((b.x + b.y) + (b.z + b.w));
    }
}

// ---------------------------------------------------------------------------
// Kernel C: O = (1/sum) * P(fp16) · V. grid (16,32). f16 MMA, V fp16 hi/lo.
// ---------------------------------------------------------------------------
extern "C" __global__ void __launch_bounds__(256)
pv_kernel(const float* __restrict__ V, float* __restrict__ Out)
{
    const int bz = blockIdx.y;
    const int qt = blockIdx.x * 64;
    const float* Vb = V + (size_t)bz * TK_ * D_;
    const __half* Pb = g_P + (size_t)bz * TQ_ * TK_;

    __shared__ __half Ah[64][STRD];   // P chunk fp16
    __shared__ float Vs[64][68];      // V chunk fp32 [k][d]
    __shared__ float invs[64];

    const int tid = threadIdx.x;
    if (tid < 64) {
        const float* ps = &g_psum[((size_t)bz * TQ_ + qt + tid) * 8];
        float4 a = *(const float4*)ps;
        float4 b = *(const float4*)(ps + 4);
        invs[tid] = 1.0f / (((a.x + a.y) + (a.z + a.w)) + ((b.x + b.y) + (b.z + b.w)));
    }
    __syncthreads();

    const int wid = tid >> 5, lane = tid & 31;
    const int g = lane >> 2, tg = lane & 3;
    const int wm = (wid >> 2) * 32;
    const int wn = (wid & 3) * 16;

    float c[2][2][4] = {};

    for (int kt = 0; kt < TK_; kt += 64) {
#pragma unroll
        for (int i = 0; i < 4; i++) {
            int t2 = tid + i * 256;        // 1024 uint2 over 64x64 halves
            int r  = t2 >> 4;
            int kc = (t2 & 15) * 4;
            *(uint2*)&Ah[r][kc] =
                *(const uint2*)(Pb + (size_t)(qt + r) * TK_ + kt + kc);
        }
#pragma unroll
        for (int i = 0; i < 4; i++) {
            int t4 = tid + i * 256;
            int k  = t4 >> 4;
            int dc = (t4 & 15) * 4;
            *(float4*)&Vs[k][dc] = *(const float4*)(Vb + (size_t)(kt + k) * D_ + dc);
        }
        __syncthreads();

#pragma unroll
        for (int k0 = 0; k0 < 64; k0 += 16) {
            u32 a[2][4], bh[2][2], bl[2][2];
#pragma unroll
            for (int mi = 0; mi < 2; mi++) {
                const __half* ph = &Ah[wm + mi * 16 + g][k0 + 2 * tg];
                a[mi][0] = *(const u32*)(ph);
                a[mi][1] = *(const u32*)(ph + 8 * STRD);
                a[mi][2] = *(const u32*)(ph + 8);
                a[mi][3] = *(const u32*)(ph + 8 * STRD + 8);
            }
#pragma unroll
            for (int ni = 0; ni < 2; ni++) {
                const int n = wn + ni * 8 + g;
                const int kb = k0 + 2 * tg;
                split2h(Vs[kb][n],     Vs[kb + 1][n], bh[ni][0], bl[ni][0]);
                split2h(Vs[kb + 8][n], Vs[kb + 9][n], bh[ni][1], bl[ni][1]);
            }
#pragma unroll
            for (int mi = 0; mi < 2; mi++)
#pragma unroll
                for (int ni = 0; ni < 2; ni++) {
                    mma_f16(c[mi][ni], a[mi][0], a[mi][1], a[mi][2], a[mi][3],
                            bh[ni][0], bh[ni][1]);
                    mma_f16(c[mi][ni], a[mi][0], a[mi][1], a[mi][2], a[mi][3],
                            bl[ni][0], bl[ni][1]);
                }
        }
        __syncthreads();
    }

#pragma unroll
    for (int mi = 0; mi < 2; mi++)
#pragma unroll
        for (int ni = 0; ni < 2; ni++) {
            int m = wm + mi * 16 + g;
            int n = wn + ni * 8 + 2 * tg;
            float inv0 = invs[m], inv1 = invs[m + 8];
            float* d0 = Out + ((size_t)bz * TQ_ + qt + m) * D_ + n;
            *(float2*)d0 = make_float2(c[mi][ni][0] * inv0, c[mi][ni][1] * inv0);
            float* d1 = Out + ((size_t)bz * TQ_ + qt + m + 8) * D_ + n;
            *(float2*)d1 = make_float2(c[mi][ni][2] * inv1, c[mi][ni][3] * inv1);
        }
}

// ---------------------------------------------------------------------------
// Kernel D: O += (1/sum) * P(fp16) · pos_v[q]. grid (1024). f16 MMA.
// ---------------------------------------------------------------------------
extern "C" __global__ void __launch_bounds__(256)
posv_kernel(const float* __restrict__ PV, float* __restrict__ Out)
{
    const int q = blockIdx.x;

    __shared__ __half Ah[32][STRD];   // P chunk fp16
    __shared__ float PVs[64][68];     // pos_v chunk fp32 [k][d]
    __shared__ float invs[B_];

    const int tid = threadIdx.x;
    if (tid < B_) {
        const float* ps = &g_psum[((size_t)tid * TQ_ + q) * 8];
        float4 a = *(const float4*)ps;
        float4 b = *(const float4*)(ps + 4);
        invs[tid] = 1.0f / (((a.x + a.y) + (a.z + a.w)) + ((b.x + b.y) + (b.z + b.w)));
    }
    __syncthreads();

    const int wid = tid >> 5, lane = tid & 31;
    const int g = lane >> 2, tg = lane & 3;
    const int wn = wid * 8;

    float c[2][4] = {};

    for (int kt = 0; kt < TK_; kt += 64) {
#pragma unroll
        for (int i = 0; i < 2; i++) {
            int t2 = tid + i * 256;        // 512 uint2 over 32x64 halves
            int bb = t2 >> 4;
            int kc = (t2 & 15) * 4;
            *(uint2*)&Ah[bb][kc] =
                *(const uint2*)(g_P + ((size_t)bb * TQ_ + q) * TK_ + kt + kc);
        }
        const float* PVq = PV + ((size_t)q * TK_ + kt) * D_;
#pragma unroll
        for (int i = 0; i < 4; i++) {
            int t4 = tid + i * 256;
            int k  = t4 >> 4;
            int dc = (t4 & 15) * 4;
            *(float4*)&PVs[k][dc] = *(const float4*)(PVq + (size_t)k * D_ + dc);
        }
        __syncthreads();

#pragma unroll
        for (int k0 = 0; k0 < 64; k0 += 16) {
            u32 a[2][4], bh[2], bl[2];
#pragma unroll
            for (int mi = 0; mi < 2; mi++) {
                const __half* ph = &Ah[mi * 16 + g][k0 + 2 * tg];
                a[mi][0] = *(const u32*)(ph);
                a[mi][1] = *(const u32*)(ph + 8 * STRD);
                a[mi][2] = *(const u32*)(ph + 8);
                a[mi][3] = *(const u32*)(ph + 8 * STRD + 8);
            }
            {
                const int n = wn + g;
                const int kb = k0 + 2 * tg;
                split2h(PVs[kb][n],     PVs[kb + 1][n], bh[0], bl[0]);
                split2h(PVs[kb + 8][n], PVs[kb + 9][n], bh[1], bl[1]);
            }
#pragma unroll
            for (int mi = 0; mi < 2; mi++) {
                mma_f16(c[mi], a[mi][0], a[mi][1], a[mi][2], a[mi][3], bh[0], bh[1]);
                mma_f16(c[mi], a[mi][0], a[mi][1], a[mi][2], a[mi][3], bl[0], bl[1]);
            }
        }
        __syncthreads();
    }

#pragma unroll
    for (int mi = 0; mi < 2; mi++) {
        const int b0 = mi * 16 + g;
        const int b1 = b0 + 8;
        const int n  = wn + 2 * tg;
        float* d0 = Out + ((size_t)b0 * TQ_ + q) * D_ + n;
        float2 o0 = *(float2*)d0;
        o0.x += c[mi][0] * invs[b0];
        o0.y += c[mi][1] * invs[b0];
        *(float2*)d0 = o0;
        float* d1 = Out + ((size_t)b1 * TQ_ + q) * D_ + n;
        float2 o1 = *(float2*)d1;
        o1.x += c[mi][2] * invs[b1];
        o1.y += c[mi][3] * invs[b1];
        *(float2*)d1 = o1;
    }
}

// ---------------------------------------------------------------------------
extern "C" void kernel_launch(void* const* d_in, const int* in_sizes, int n_in,
                              void* d_out, int out_size)
{
    const float* Q  = (const float*)d_in[0];
    const float* K  = (const float*)d_in[1];
    const float* V  = (const float*)d_in[2];
    const float* PK = (const float*)d_in[3];
    const float* PV = (const float*)d_in[4];
    const int*   VL = (const int*)d_in[5];
    float* Out = (float*)d_out;

    qk_kernel<<<dim3(TK_ / 64, TQ_ / 64, B_), 256>>>(Q, K);
    posk_kernel<<<dim3(TK_ / 128, TQ_), 256>>>(Q, PK, VL);
    pv_kernel<<<dim3(TQ_ / 64, B_), 256>>>(V, Out);
    posv_kernel<<<TQ_, 256>>>(PV, Out);
}

// round 7
// speedup vs baseline: 4.3510x; 1.1155x over previous
#include <cuda_runtime.h>
#include <cuda_bf16.h>
#include <cuda_fp16.h>
#include <math.h>

typedef unsigned u32;

#define B_  32
#define TQ_ 1024
#define TK_ 1024
#define D_  64
#define STRD 72   // smem row stride in 2B elems (64 data + 8 pad): conflict-free frags
#define VSTR 68   // fp32 V-tile row stride (conflict-free for split reads)

// scratch: fp32 scores, fp16 probs, per-(b,q) 8-block partial rowsums
static __device__ float  g_S[(size_t)B_ * TQ_ * TK_];
static __device__ __half g_P[(size_t)B_ * TQ_ * TK_];
static __device__ float  g_psum[(size_t)B_ * TQ_ * 8];

// ---- mma helpers ----------------------------------------------------------
__device__ __forceinline__ void mma_bf16(float c[4], u32 a0, u32 a1, u32 a2, u32 a3,
                                         u32 b0, u32 b1)
{
    asm volatile(
        "mma.sync.aligned.m16n8k16.row.col.f32.bf16.bf16.f32 "
        "{%0,%1,%2,%3},{%4,%5,%6,%7},{%8,%9},{%0,%1,%2,%3};\n"
        : "+f"(c[0]), "+f"(c[1]), "+f"(c[2]), "+f"(c[3])
        : "r"(a0), "r"(a1), "r"(a2), "r"(a3), "r"(b0), "r"(b1));
}
__device__ __forceinline__ void mma_f16(float c[4], u32 a0, u32 a1, u32 a2, u32 a3,
                                        u32 b0, u32 b1)
{
    asm volatile(
        "mma.sync.aligned.m16n8k16.row.col.f32.f16.f16.f32 "
        "{%0,%1,%2,%3},{%4,%5,%6,%7},{%8,%9},{%0,%1,%2,%3};\n"
        : "+f"(c[0]), "+f"(c[1]), "+f"(c[2]), "+f"(c[3])
        : "r"(a0), "r"(a1), "r"(a2), "r"(a3), "r"(b0), "r"(b1));
}

__device__ __forceinline__ u32 cvt2bf(float hi, float lo) {
    u32 r;
    asm("cvt.rn.bf16x2.f32 %0,%1,%2;" : "=r"(r) : "f"(hi), "f"(lo));
    return r;
}
// bf16 hi/lo split (x0 -> low half, x1 -> high half)
__device__ __forceinline__ void split2(float x0, float x1, u32& h, u32& l) {
    h = cvt2bf(x1, x0);
    float h0 = __uint_as_float(h << 16);
    float h1 = __uint_as_float(h & 0xffff0000u);
    l = cvt2bf(x1 - h1, x0 - h0);
}
// fp16 hi/lo split
__device__ __forceinline__ void split2h(float x0, float x1, u32& h, u32& l) {
    __half2 hh = __floats2half2_rn(x0, x1);
    h = *(u32*)&hh;
    float2 hf = __half22float2(hh);
    __half2 ll = __floats2half2_rn(x0 - hf.x, x1 - hf.y);
    l = *(u32*)&ll;
}

// ---- cp.async helpers -----------------------------------------------------
__device__ __forceinline__ void cp16(void* dst_smem, const void* src) {
    u32 d = (u32)__cvta_generic_to_shared(dst_smem);
    asm volatile("cp.async.cg.shared.global [%0], [%1], 16;\n" :: "r"(d), "l"(src));
}
#define CP_COMMIT() asm volatile("cp.async.commit_group;\n" ::)
#define CP_WAIT1()  asm volatile("cp.async.wait_group 1;\n" ::)
#define CP_WAIT0()  asm volatile("cp.async.wait_group 0;\n" ::)

// ---------------------------------------------------------------------------
// Kernel A: S[b,q,k] = Q[b,q,:]·K[b,k,:] (unscaled, fp32 out). bf16x3 MMA.
// ---------------------------------------------------------------------------
extern "C" __global__ void __launch_bounds__(256)
qk_kernel(const float* __restrict__ Q, const float* __restrict__ K)
{
    const int bz = blockIdx.z;
    const int qt = blockIdx.y * 64;
    const int kt = blockIdx.x * 64;
    const float* Qb = Q + (size_t)bz * TQ_ * D_;
    const float* Kb = K + (size_t)bz * TK_ * D_;
    float* Sb = g_S + (size_t)bz * TQ_ * TK_;

    __shared__ __nv_bfloat16 Ah[64][STRD], Al[64][STRD];
    __shared__ __nv_bfloat16 Bh[64][STRD], Bl[64][STRD];

    const int tid = threadIdx.x;
#pragma unroll
    for (int i = 0; i < 4; i++) {
        int t4  = tid + i * 256;
        int row = t4 >> 4;
        int col = (t4 & 15) * 4;
        float4 v = *(const float4*)(Qb + (size_t)(qt + row) * D_ + col);
        u32 h0, l0, h1, l1;
        split2(v.x, v.y, h0, l0); split2(v.z, v.w, h1, l1);
        *(uint2*)&Ah[row][col] = make_uint2(h0, h1);
        *(uint2*)&Al[row][col] = make_uint2(l0, l1);
        float4 w = *(const float4*)(Kb + (size_t)(kt + row) * D_ + col);
        split2(w.x, w.y, h0, l0); split2(w.z, w.w, h1, l1);
        *(uint2*)&Bh[row][col] = make_uint2(h0, h1);
        *(uint2*)&Bl[row][col] = make_uint2(l0, l1);
    }
    __syncthreads();

    const int wid = tid >> 5, lane = tid & 31;
    const int g = lane >> 2, tg = lane & 3;
    const int wm = (wid >> 2) * 32;
    const int wn = (wid & 3) * 16;

    float c[2][2][4] = {};

#pragma unroll
    for (int k0 = 0; k0 < 64; k0 += 16) {
        u32 ah[2][4], al[2][4], bh[2][2], bl[2][2];
#pragma unroll
        for (int mi = 0; mi < 2; mi++) {
            const __nv_bfloat16* ph = &Ah[wm + mi * 16 + g][k0 + 2 * tg];
            ah[mi][0] = *(const u32*)(ph);
            ah[mi][1] = *(const u32*)(ph + 8 * STRD);
            ah[mi][2] = *(const u32*)(ph + 8);
            ah[mi][3] = *(const u32*)(ph + 8 * STRD + 8);
            const __nv_bfloat16* pl = &Al[wm + mi * 16 + g][k0 + 2 * tg];
            al[mi][0] = *(const u32*)(pl);
            al[mi][1] = *(const u32*)(pl + 8 * STRD);
            al[mi][2] = *(const u32*)(pl + 8);
            al[mi][3] = *(const u32*)(pl + 8 * STRD + 8);
        }
#pragma unroll
        for (int ni = 0; ni < 2; ni++) {
            const __nv_bfloat16* ph = &Bh[wn + ni * 8 + g][k0 + 2 * tg];
            bh[ni][0] = *(const u32*)(ph);
            bh[ni][1] = *(const u32*)(ph + 8);
            const __nv_bfloat16* pl = &Bl[wn + ni * 8 + g][k0 + 2 * tg];
            bl[ni][0] = *(const u32*)(pl);
            bl[ni][1] = *(const u32*)(pl + 8);
        }
#pragma unroll
        for (int mi = 0; mi < 2; mi++)
#pragma unroll
            for (int ni = 0; ni < 2; ni++) {
                mma_bf16(c[mi][ni], ah[mi][0], ah[mi][1], ah[mi][2], ah[mi][3],
                         bh[ni][0], bh[ni][1]);
                mma_bf16(c[mi][ni], al[mi][0], al[mi][1], al[mi][2], al[mi][3],
                         bh[ni][0], bh[ni][1]);
                mma_bf16(c[mi][ni], ah[mi][0], ah[mi][1], ah[mi][2], ah[mi][3],
                         bl[ni][0], bl[ni][1]);
            }
    }

#pragma unroll
    for (int mi = 0; mi < 2; mi++)
#pragma unroll
        for (int ni = 0; ni < 2; ni++) {
            int m = qt + wm + mi * 16 + g;
            int n = kt + wn + ni * 8 + 2 * tg;
            *(float2*)&Sb[(size_t)m * TK_ + n] =
                make_float2(c[mi][ni][0], c[mi][ni][1]);
            *(float2*)&Sb[(size_t)(m + 8) * TK_ + n] =
                make_float2(c[mi][ni][2], c[mi][ni][3]);
        }
}

// ---------------------------------------------------------------------------
// Kernel B: P(fp16) = exp(mask((S + Q·pos_k)/8)); emits partial rowsums of
// the fp16-ROUNDED values (exactly consistent normalization).
// ---------------------------------------------------------------------------
extern "C" __global__ void __launch_bounds__(256)
posk_kernel(const float* __restrict__ Q, const float* __restrict__ PK,
            const int* __restrict__ VL)
{
    const int q  = blockIdx.y;
    const int kt = blockIdx.x * 128;

    __shared__ __nv_bfloat16 Ah[32][STRD], Al[32][STRD];
    __shared__ __nv_bfloat16 Bh[128][STRD], Bl[128][STRD];
    __shared__ float rsum[32][8];
    __shared__ int vls[B_];

    const int tid = threadIdx.x;
#pragma unroll
    for (int i = 0; i < 2; i++) {
        int t4  = tid + i * 256;
        int row = t4 >> 4;
        int col = (t4 & 15) * 4;
        float4 v = *(const float4*)(Q + ((size_t)row * TQ_ + q) * D_ + col);
        u32 h0, l0, h1, l1;
        split2(v.x, v.y, h0, l0); split2(v.z, v.w, h1, l1);
        *(uint2*)&Ah[row][col] = make_uint2(h0, h1);
        *(uint2*)&Al[row][col] = make_uint2(l0, l1);
    }
    const float* PKq = PK + ((size_t)q * TK_ + kt) * D_;
#pragma unroll
    for (int i = 0; i < 8; i++) {
        int t4  = tid + i * 256;
        int row = t4 >> 4;
        int col = (t4 & 15) * 4;
        float4 v = *(const float4*)(PKq + (size_t)row * D_ + col);
        u32 h0, l0, h1, l1;
        split2(v.x, v.y, h0, l0); split2(v.z, v.w, h1, l1);
        *(uint2*)&Bh[row][col] = make_uint2(h0, h1);
        *(uint2*)&Bl[row][col] = make_uint2(l0, l1);
    }
    if (tid < B_) vls[tid] = VL[tid];
    __syncthreads();

    const int wid = tid >> 5, lane = tid & 31;
    const int g = lane >> 2, tg = lane & 3;
    const int wn = wid * 16;

    float c[2][2][4] = {};

#pragma unroll
    for (int k0 = 0; k0 < 64; k0 += 16) {
        u32 ah[2][4], al[2][4], bh[2][2], bl[2][2];
#pragma unroll
        for (int mi = 0; mi < 2; mi++) {
            const __nv_bfloat16* ph = &Ah[mi * 16 + g][k0 + 2 * tg];
            ah[mi][0] = *(const u32*)(ph);
            ah[mi][1] = *(const u32*)(ph + 8 * STRD);
            ah[mi][2] = *(const u32*)(ph + 8);
            ah[mi][3] = *(const u32*)(ph + 8 * STRD + 8);
            const __nv_bfloat16* pl = &Al[mi * 16 + g][k0 + 2 * tg];
            al[mi][0] = *(const u32*)(pl);
            al[mi][1] = *(const u32*)(pl + 8 * STRD);
            al[mi][2] = *(const u32*)(pl + 8);
            al[mi][3] = *(const u32*)(pl + 8 * STRD + 8);
        }
#pragma unroll
        for (int ni = 0; ni < 2; ni++) {
            const __nv_bfloat16* ph = &Bh[wn + ni * 8 + g][k0 + 2 * tg];
            bh[ni][0] = *(const u32*)(ph);
            bh[ni][1] = *(const u32*)(ph + 8);
            const __nv_bfloat16* pl = &Bl[wn + ni * 8 + g][k0 + 2 * tg];
            bl[ni][0] = *(const u32*)(pl);
            bl[ni][1] = *(const u32*)(pl + 8);
        }
#pragma unroll
        for (int mi = 0; mi < 2; mi++)
#pragma unroll
            for (int ni = 0; ni < 2; ni++) {
                mma_bf16(c[mi][ni], ah[mi][0], ah[mi][1], ah[mi][2], ah[mi][3],
                         bh[ni][0], bh[ni][1]);
                mma_bf16(c[mi][ni], al[mi][0], al[mi][1], al[mi][2], al[mi][3],
                         bh[ni][0], bh[ni][1]);
                mma_bf16(c[mi][ni], ah[mi][0], ah[mi][1], ah[mi][2], ah[mi][3],
                         bl[ni][0], bl[ni][1]);
            }
    }

    // epilogue: read S, add, mask, exp, round to fp16, store P, sum rounded
    float rs[2][2] = {};
#pragma unroll
    for (int mi = 0; mi < 2; mi++) {
        const int b0  = mi * 16 + g;
        const int b1  = b0 + 8;
        const int vl0 = vls[b0];
        const int vl1 = vls[b1];
#pragma unroll
        for (int ni = 0; ni < 2; ni++) {
            const int col = kt + wn + ni * 8 + 2 * tg;
            {
                float2 s0 = *(const float2*)&g_S[((size_t)b0 * TQ_ + q) * TK_ + col];
                float e0 = (col     < vl0) ? __expf((s0.x + c[mi][ni][0]) * 0.125f) : 0.f;
                float e1 = (col + 1 < vl0) ? __expf((s0.y + c[mi][ni][1]) * 0.125f) : 0.f;
                __half2 hp = __floats2half2_rn(e0, e1);
                *(__half2*)&g_P[((size_t)b0 * TQ_ + q) * TK_ + col] = hp;
                float2 er = __half22float2(hp);
                rs[mi][0] += er.x + er.y;
            }
            {
                float2 s1 = *(const float2*)&g_S[((size_t)b1 * TQ_ + q) * TK_ + col];
                float e0 = (col     < vl1) ? __expf((s1.x + c[mi][ni][2]) * 0.125f) : 0.f;
                float e1 = (col + 1 < vl1) ? __expf((s1.y + c[mi][ni][3]) * 0.125f) : 0.f;
                __half2 hp = __floats2half2_rn(e0, e1);
                *(__half2*)&g_P[((size_t)b1 * TQ_ + q) * TK_ + col] = hp;
                float2 er = __half22float2(hp);
                rs[mi][1] += er.x + er.y;
            }
        }
    }
#pragma unroll
    for (int mi = 0; mi < 2; mi++)
#pragma unroll
        for (int r = 0; r < 2; r++) {
            rs[mi][r] += __shfl_xor_sync(0xffffffffu, rs[mi][r], 1);
            rs[mi][r] += __shfl_xor_sync(0xffffffffu, rs[mi][r], 2);
        }
    if (tg == 0) {
#pragma unroll
        for (int mi = 0; mi < 2; mi++) {
            rsum[mi * 16 + g][wid]     = rs[mi][0];
            rsum[mi * 16 + g + 8][wid] = rs[mi][1];
        }
    }
    __syncthreads();
    if (tid < 32) {
        float4 a = *(float4*)&rsum[tid][0];
        float4 b = *(float4*)&rsum[tid][4];
        g_psum[((size_t)tid * TQ_ + q) * 8 + blockIdx.x] =
            ((a.x + a.y) + (a.z + a.w)) + ((b.x + b.y) + (b.z + b.w));
    }
}

// ---------------------------------------------------------------------------
// Kernel C: O = (1/sum) * P(fp16) · V. grid (16,32). f16 MMA.
// 2-stage cp.async pipeline; dynamic smem (53.5 KB).
// ---------------------------------------------------------------------------
#define PV_AH_BYTES (2 * 64 * STRD * 2)
#define PV_VS_BYTES (2 * 64 * VSTR * 4)
#define PV_SMEM     (PV_AH_BYTES + PV_VS_BYTES + 64 * 4)

extern "C" __global__ void __launch_bounds__(256)
pv_kernel(const float* __restrict__ V, float* __restrict__ Out)
{
    extern __shared__ char dynbuf[];
    __half* AhB  = (__half*)dynbuf;                       // [2][64][STRD]
    float*  VsB  = (float*)(dynbuf + PV_AH_BYTES);        // [2][64][VSTR]
    float*  invs = (float*)(dynbuf + PV_AH_BYTES + PV_VS_BYTES);

    const int bz = blockIdx.y;
    const int qt = blockIdx.x * 64;
    const float* Vb = V + (size_t)bz * TK_ * D_;
    const __half* Pb = g_P + (size_t)bz * TQ_ * TK_;

    const int tid = threadIdx.x;
    if (tid < 64) {
        const float* ps = &g_psum[((size_t)bz * TQ_ + qt + tid) * 8];
        float4 a = *(const float4*)ps;
        float4 b = *(const float4*)(ps + 4);
        invs[tid] = 1.0f / (((a.x + a.y) + (a.z + a.w)) + ((b.x + b.y) + (b.z + b.w)));
    }

    auto load_stage = [&](int s, int kt) {
        __half* A = AhB + s * 64 * STRD;
        float*  Vt = VsB + s * 64 * VSTR;
#pragma unroll
        for (int i = 0; i < 2; i++) {          // P: 512 x 16B
            int idx = tid + i * 256;
            int r  = idx >> 3;
            int kc = (idx & 7) * 8;
            cp16(A + r * STRD + kc, Pb + (size_t)(qt + r) * TK_ + kt + kc);
        }
#pragma unroll
        for (int i = 0; i < 4; i++) {          // V: 1024 x 16B
            int idx = tid + i * 256;
            int k  = idx >> 4;
            int dc = (idx & 15) * 4;
            cp16(Vt + k * VSTR + dc, Vb + (size_t)(kt + k) * D_ + dc);
        }
        CP_COMMIT();
    };

    const int wid = tid >> 5, lane = tid & 31;
    const int g = lane >> 2, tg = lane & 3;
    const int wm = (wid >> 2) * 32;
    const int wn = (wid & 3) * 16;

    float c[2][2][4] = {};

    load_stage(0, 0);
    for (int ci = 0; ci < 16; ci++) {
        const int s = ci & 1;
        if (ci < 15) { load_stage(s ^ 1, (ci + 1) * 64); CP_WAIT1(); }
        else         { CP_WAIT0(); }
        __syncthreads();

        const __half* A = AhB + s * 64 * STRD;
        const float*  Vt = VsB + s * 64 * VSTR;
#pragma unroll
        for (int k0 = 0; k0 < 64; k0 += 16) {
            u32 a[2][4], bh[2][2], bl[2][2];
#pragma unroll
            for (int mi = 0; mi < 2; mi++) {
                const __half* ph = A + (wm + mi * 16 + g) * STRD + k0 + 2 * tg;
                a[mi][0] = *(const u32*)(ph);
                a[mi][1] = *(const u32*)(ph + 8 * STRD);
                a[mi][2] = *(const u32*)(ph + 8);
                a[mi][3] = *(const u32*)(ph + 8 * STRD + 8);
            }
#pragma unroll
            for (int ni = 0; ni < 2; ni++) {
                const int n = wn + ni * 8 + g;
                const int kb = k0 + 2 * tg;
                split2h(Vt[kb * VSTR + n],       Vt[(kb + 1) * VSTR + n], bh[ni][0], bl[ni][0]);
                split2h(Vt[(kb + 8) * VSTR + n], Vt[(kb + 9) * VSTR + n], bh[ni][1], bl[ni][1]);
            }
#pragma unroll
            for (int mi = 0; mi < 2; mi++)
#pragma unroll
                for (int ni = 0; ni < 2; ni++) {
                    mma_f16(c[mi][ni], a[mi][0], a[mi][1], a[mi][2], a[mi][3],
                            bh[ni][0], bh[ni][1]);
                    mma_f16(c[mi][ni], a[mi][0], a[mi][1], a[mi][2], a[mi][3],
                            bl[ni][0], bl[ni][1]);
                }
        }
        __syncthreads();
    }

#pragma unroll
    for (int mi = 0; mi < 2; mi++)
#pragma unroll
        for (int ni = 0; ni < 2; ni++) {
            int m = wm + mi * 16 + g;
            int n = wn + ni * 8 + 2 * tg;
            float inv0 = invs[m], inv1 = invs[m + 8];
            float* d0 = Out + ((size_t)bz * TQ_ + qt + m) * D_ + n;
            *(float2*)d0 = make_float2(c[mi][ni][0] * inv0, c[mi][ni][1] * inv0);
            float* d1 = Out + ((size_t)bz * TQ_ + qt + m + 8) * D_ + n;
            *(float2*)d1 = make_float2(c[mi][ni][2] * inv1, c[mi][ni][3] * inv1);
        }
}

// ---------------------------------------------------------------------------
// Kernel D: O += (1/sum) * P(fp16) · pos_v[q]. grid (1024). f16 MMA.
// 2-stage cp.async pipeline; static smem (44.2 KB).
// ---------------------------------------------------------------------------
extern "C" __global__ void __launch_bounds__(256)
posv_kernel(const float* __restrict__ PV, float* __restrict__ Out)
{
    const int q = blockIdx.x;

    __shared__ __half Ahs[2][32][STRD];   // P chunks fp16
    __shared__ float  PVs[2][64][VSTR];   // pos_v chunks fp32 [k][d]
    __shared__ float  invs[B_];

    const int tid = threadIdx.x;
    if (tid < B_) {
        const float* ps = &g_psum[((size_t)tid * TQ_ + q) * 8];
        float4 a = *(const float4*)ps;
        float4 b = *(const float4*)(ps + 4);
        invs[tid] = 1.0f / (((a.x + a.y) + (a.z + a.w)) + ((b.x + b.y) + (b.z + b.w)));
    }

    auto load_stage = [&](int s, int kt) {
        {                                       // P: 256 x 16B
            int bb = tid >> 3;
            int kc = (tid & 7) * 8;
            cp16(&Ahs[s][bb][kc], g_P + ((size_t)bb * TQ_ + q) * TK_ + kt + kc);
        }
        const float* PVq = PV + ((size_t)q * TK_ + kt) * D_;
#pragma unroll
        for (int i = 0; i < 4; i++) {           // pos_v: 1024 x 16B
            int idx = tid + i * 256;
            int k  = idx >> 4;
            int dc = (idx & 15) * 4;
            cp16(&PVs[s][k][dc], PVq + (size_t)k * D_ + dc);
        }
        CP_COMMIT();
    };

    const int wid = tid >> 5, lane = tid & 31;
    const int g = lane >> 2, tg = lane & 3;
    const int wn = wid * 8;

    float c[2][4] = {};

    load_stage(0, 0);
    for (int ci = 0; ci < 16; ci++) {
        const int s = ci & 1;
        if (ci < 15) { load_stage(s ^ 1, (ci + 1) * 64); CP_WAIT1(); }
        else         { CP_WAIT0(); }
        __syncthreads();

#pragma unroll
        for (int k0 = 0; k0 < 64; k0 += 16) {
            u32 a[2][4], bh[2], bl[2];
#pragma unroll
            for (int mi = 0; mi < 2; mi++) {
                const __half* ph = &Ahs[s][mi * 16 + g][k0 + 2 * tg];
                a[mi][0] = *(const u32*)(ph);
                a[mi][1] = *(const u32*)(ph + 8 * STRD);
                a[mi][2] = *(const u32*)(ph + 8);
                a[mi][3] = *(const u32*)(ph + 8 * STRD + 8);
            }
            {
                const int n = wn + g;
                const int kb = k0 + 2 * tg;
                split2h(PVs[s][kb][n],     PVs[s][kb + 1][n], bh[0], bl[0]);
                split2h(PVs[s][kb + 8][n], PVs[s][kb + 9][n], bh[1], bl[1]);
            }
#pragma unroll
            for (int mi = 0; mi < 2; mi++) {
                mma_f16(c[mi], a[mi][0], a[mi][1], a[mi][2], a[mi][3], bh[0], bh[1]);
                mma_f16(c[mi], a[mi][0], a[mi][1], a[mi][2], a[mi][3], bl[0], bl[1]);
            }
        }
        __syncthreads();
    }

#pragma unroll
    for (int mi = 0; mi < 2; mi++) {
        const int b0 = mi * 16 + g;
        const int b1 = b0 + 8;
        const int n  = wn + 2 * tg;
        float* d0 = Out + ((size_t)b0 * TQ_ + q) * D_ + n;
        float2 o0 = *(float2*)d0;
        o0.x += c[mi][0] * invs[b0];
        o0.y += c[mi][1] * invs[b0];
        *(float2*)d0 = o0;
        float* d1 = Out + ((size_t)b1 * TQ_ + q) * D_ + n;
        float2 o1 = *(float2*)d1;
        o1.x += c[mi][2] * invs[b1];
        o1.y += c[mi][3] * invs[b1];
        *(float2*)d1 = o1;
    }
}

// ---------------------------------------------------------------------------
extern "C" void kernel_launch(void* const* d_in, const int* in_sizes, int n_in,
                              void* d_out, int out_size)
{
    const float* Q  = (const float*)d_in[0];
    const float* K  = (const float*)d_in[1];
    const float* V  = (const float*)d_in[2];
    const float* PK = (const float*)d_in[3];
    const float* PV = (const float*)d_in[4];
    const int*   VL = (const int*)d_in[5];
    float* Out = (float*)d_out;

    cudaFuncSetAttribute(pv_kernel, cudaFuncAttributeMaxDynamicSharedMemorySize,
                         PV_SMEM);

    qk_kernel<<<dim3(TK_ / 64, TQ_ / 64, B_), 256>>>(Q, K);
    posk_kernel<<<dim3(TK_ / 128, TQ_), 256>>>(Q, PK, VL);
    pv_kernel<<<dim3(TQ_ / 64, B_), 256, PV_SMEM>>>(V, Out);
    posv_kernel<<<TQ_, 256>>>(PV, Out);
}

// round 8
// speedup vs baseline: 4.4669x; 1.0266x over previous
#include <cuda_runtime.h>
#include <cuda_bf16.h>
#include <cuda_fp16.h>
#include <math.h>

typedef unsigned u32;

#define B_  32
#define TQ_ 1024
#define TK_ 1024
#define D_  64
#define STRD 72   // smem row stride in 2B elems (64 data + 8 pad): conflict-free frags
#define VSTR 68   // fp32 V-tile row stride (conflict-free for split reads)

// scratch: fp16 scores, fp16 probs, per-(b,q) 8-block partial rowsums
static __device__ __half g_S[(size_t)B_ * TQ_ * TK_];
static __device__ __half g_P[(size_t)B_ * TQ_ * TK_];
static __device__ float  g_psum[(size_t)B_ * TQ_ * 8];

// ---- mma helpers ----------------------------------------------------------
__device__ __forceinline__ void mma_bf16(float c[4], u32 a0, u32 a1, u32 a2, u32 a3,
                                         u32 b0, u32 b1)
{
    asm volatile(
        "mma.sync.aligned.m16n8k16.row.col.f32.bf16.bf16.f32 "
        "{%0,%1,%2,%3},{%4,%5,%6,%7},{%8,%9},{%0,%1,%2,%3};\n"
        : "+f"(c[0]), "+f"(c[1]), "+f"(c[2]), "+f"(c[3])
        : "r"(a0), "r"(a1), "r"(a2), "r"(a3), "r"(b0), "r"(b1));
}
__device__ __forceinline__ void mma_f16(float c[4], u32 a0, u32 a1, u32 a2, u32 a3,
                                        u32 b0, u32 b1)
{
    asm volatile(
        "mma.sync.aligned.m16n8k16.row.col.f32.f16.f16.f32 "
        "{%0,%1,%2,%3},{%4,%5,%6,%7},{%8,%9},{%0,%1,%2,%3};\n"
        : "+f"(c[0]), "+f"(c[1]), "+f"(c[2]), "+f"(c[3])
        : "r"(a0), "r"(a1), "r"(a2), "r"(a3), "r"(b0), "r"(b1));
}

__device__ __forceinline__ u32 cvt2bf(float hi, float lo) {
    u32 r;
    asm("cvt.rn.bf16x2.f32 %0,%1,%2;" : "=r"(r) : "f"(hi), "f"(lo));
    return r;
}
// bf16 hi/lo split (x0 -> low half, x1 -> high half)
__device__ __forceinline__ void split2(float x0, float x1, u32& h, u32& l) {
    h = cvt2bf(x1, x0);
    float h0 = __uint_as_float(h << 16);
    float h1 = __uint_as_float(h & 0xffff0000u);
    l = cvt2bf(x1 - h1, x0 - h0);
}
// fp16 hi/lo split
__device__ __forceinline__ void split2h(float x0, float x1, u32& h, u32& l) {
    __half2 hh = __floats2half2_rn(x0, x1);
    h = *(u32*)&hh;
    float2 hf = __half22float2(hh);
    __half2 ll = __floats2half2_rn(x0 - hf.x, x1 - hf.y);
    l = *(u32*)&ll;
}

// ---- cp.async helpers -----------------------------------------------------
__device__ __forceinline__ void cp16(void* dst_smem, const void* src) {
    u32 d = (u32)__cvta_generic_to_shared(dst_smem);
    asm volatile("cp.async.cg.shared.global [%0], [%1], 16;\n" :: "r"(d), "l"(src));
}
#define CP_COMMIT() asm volatile("cp.async.commit_group;\n" ::)
#define CP_WAIT1()  asm volatile("cp.async.wait_group 1;\n" ::)
#define CP_WAIT0()  asm volatile("cp.async.wait_group 0;\n" ::)

// ---------------------------------------------------------------------------
// Kernel A: S[b,q,k] = Q[b,q,:]·K[b,k,:] (unscaled, fp16 out). bf16x3 MMA.
// ---------------------------------------------------------------------------
extern "C" __global__ void __launch_bounds__(256)
qk_kernel(const float* __restrict__ Q, const float* __restrict__ K)
{
    const int bz = blockIdx.z;
    const int qt = blockIdx.y * 64;
    const int kt = blockIdx.x * 64;
    const float* Qb = Q + (size_t)bz * TQ_ * D_;
    const float* Kb = K + (size_t)bz * TK_ * D_;
    __half* Sb = g_S + (size_t)bz * TQ_ * TK_;

    __shared__ __nv_bfloat16 Ah[64][STRD], Al[64][STRD];
    __shared__ __nv_bfloat16 Bh[64][STRD], Bl[64][STRD];

    const int tid = threadIdx.x;
#pragma unroll
    for (int i = 0; i < 4; i++) {
        int t4  = tid + i * 256;
        int row = t4 >> 4;
        int col = (t4 & 15) * 4;
        float4 v = *(const float4*)(Qb + (size_t)(qt + row) * D_ + col);
        u32 h0, l0, h1, l1;
        split2(v.x, v.y, h0, l0); split2(v.z, v.w, h1, l1);
        *(uint2*)&Ah[row][col] = make_uint2(h0, h1);
        *(uint2*)&Al[row][col] = make_uint2(l0, l1);
        float4 w = *(const float4*)(Kb + (size_t)(kt + row) * D_ + col);
        split2(w.x, w.y, h0, l0); split2(w.z, w.w, h1, l1);
        *(uint2*)&Bh[row][col] = make_uint2(h0, h1);
        *(uint2*)&Bl[row][col] = make_uint2(l0, l1);
    }
    __syncthreads();

    const int wid = tid >> 5, lane = tid & 31;
    const int g = lane >> 2, tg = lane & 3;
    const int wm = (wid >> 2) * 32;
    const int wn = (wid & 3) * 16;

    float c[2][2][4] = {};

#pragma unroll
    for (int k0 = 0; k0 < 64; k0 += 16) {
        u32 ah[2][4], al[2][4], bh[2][2], bl[2][2];
#pragma unroll
        for (int mi = 0; mi < 2; mi++) {
            const __nv_bfloat16* ph = &Ah[wm + mi * 16 + g][k0 + 2 * tg];
            ah[mi][0] = *(const u32*)(ph);
            ah[mi][1] = *(const u32*)(ph + 8 * STRD);
            ah[mi][2] = *(const u32*)(ph + 8);
            ah[mi][3] = *(const u32*)(ph + 8 * STRD + 8);
            const __nv_bfloat16* pl = &Al[wm + mi * 16 + g][k0 + 2 * tg];
            al[mi][0] = *(const u32*)(pl);
            al[mi][1] = *(const u32*)(pl + 8 * STRD);
            al[mi][2] = *(const u32*)(pl + 8);
            al[mi][3] = *(const u32*)(pl + 8 * STRD + 8);
        }
#pragma unroll
        for (int ni = 0; ni < 2; ni++) {
            const __nv_bfloat16* ph = &Bh[wn + ni * 8 + g][k0 + 2 * tg];
            bh[ni][0] = *(const u32*)(ph);
            bh[ni][1] = *(const u32*)(ph + 8);
            const __nv_bfloat16* pl = &Bl[wn + ni * 8 + g][k0 + 2 * tg];
            bl[ni][0] = *(const u32*)(pl);
            bl[ni][1] = *(const u32*)(pl + 8);
        }
#pragma unroll
        for (int mi = 0; mi < 2; mi++)
#pragma unroll
            for (int ni = 0; ni < 2; ni++) {
                mma_bf16(c[mi][ni], ah[mi][0], ah[mi][1], ah[mi][2], ah[mi][3],
                         bh[ni][0], bh[ni][1]);
                mma_bf16(c[mi][ni], al[mi][0], al[mi][1], al[mi][2], al[mi][3],
                         bh[ni][0], bh[ni][1]);
                mma_bf16(c[mi][ni], ah[mi][0], ah[mi][1], ah[mi][2], ah[mi][3],
                         bl[ni][0], bl[ni][1]);
            }
    }

#pragma unroll
    for (int mi = 0; mi < 2; mi++)
#pragma unroll
        for (int ni = 0; ni < 2; ni++) {
            int m = qt + wm + mi * 16 + g;
            int n = kt + wn + ni * 8 + 2 * tg;
            *(__half2*)&Sb[(size_t)m * TK_ + n] =
                __floats2half2_rn(c[mi][ni][0], c[mi][ni][1]);
            *(__half2*)&Sb[(size_t)(m + 8) * TK_ + n] =
                __floats2half2_rn(c[mi][ni][2], c[mi][ni][3]);
        }
}

// ---------------------------------------------------------------------------
// Kernel B: P(fp16) = exp(mask((S + Q·pos_k)/8)); emits partial rowsums of
// the fp16-ROUNDED values (exactly consistent normalization).
// ---------------------------------------------------------------------------
extern "C" __global__ void __launch_bounds__(256)
posk_kernel(const float* __restrict__ Q, const float* __restrict__ PK,
            const int* __restrict__ VL)
{
    const int q  = blockIdx.y;
    const int kt = blockIdx.x * 128;

    __shared__ __nv_bfloat16 Ah[32][STRD], Al[32][STRD];
    __shared__ __nv_bfloat16 Bh[128][STRD], Bl[128][STRD];
    __shared__ float rsum[32][8];
    __shared__ int vls[B_];

    const int tid = threadIdx.x;
#pragma unroll
    for (int i = 0; i < 2; i++) {
        int t4  = tid + i * 256;
        int row = t4 >> 4;
        int col = (t4 & 15) * 4;
        float4 v = *(const float4*)(Q + ((size_t)row * TQ_ + q) * D_ + col);
        u32 h0, l0, h1, l1;
        split2(v.x, v.y, h0, l0); split2(v.z, v.w, h1, l1);
        *(uint2*)&Ah[row][col] = make_uint2(h0, h1);
        *(uint2*)&Al[row][col] = make_uint2(l0, l1);
    }
    const float* PKq = PK + ((size_t)q * TK_ + kt) * D_;
#pragma unroll
    for (int i = 0; i < 8; i++) {
        int t4  = tid + i * 256;
        int row = t4 >> 4;
        int col = (t4 & 15) * 4;
        float4 v = *(const float4*)(PKq + (size_t)row * D_ + col);
        u32 h0, l0, h1, l1;
        split2(v.x, v.y, h0, l0); split2(v.z, v.w, h1, l1);
        *(uint2*)&Bh[row][col] = make_uint2(h0, h1);
        *(uint2*)&Bl[row][col] = make_uint2(l0, l1);
    }
    if (tid < B_) vls[tid] = VL[tid];
    __syncthreads();

    const int wid = tid >> 5, lane = tid & 31;
    const int g = lane >> 2, tg = lane & 3;
    const int wn = wid * 16;

    float c[2][2][4] = {};

#pragma unroll
    for (int k0 = 0; k0 < 64; k0 += 16) {
        u32 ah[2][4], al[2][4], bh[2][2], bl[2][2];
#pragma unroll
        for (int mi = 0; mi < 2; mi++) {
            const __nv_bfloat16* ph = &Ah[mi * 16 + g][k0 + 2 * tg];
            ah[mi][0] = *(const u32*)(ph);
            ah[mi][1] = *(const u32*)(ph + 8 * STRD);
            ah[mi][2] = *(const u32*)(ph + 8);
            ah[mi][3] = *(const u32*)(ph + 8 * STRD + 8);
            const __nv_bfloat16* pl = &Al[mi * 16 + g][k0 + 2 * tg];
            al[mi][0] = *(const u32*)(pl);
            al[mi][1] = *(const u32*)(pl + 8 * STRD);
            al[mi][2] = *(const u32*)(pl + 8);
            al[mi][3] = *(const u32*)(pl + 8 * STRD + 8);
        }
#pragma unroll
        for (int ni = 0; ni < 2; ni++) {
            const __nv_bfloat16* ph = &Bh[wn + ni * 8 + g][k0 + 2 * tg];
            bh[ni][0] = *(const u32*)(ph);
            bh[ni][1] = *(const u32*)(ph + 8);
            const __nv_bfloat16* pl = &Bl[wn + ni * 8 + g][k0 + 2 * tg];
            bl[ni][0] = *(const u32*)(pl);
            bl[ni][1] = *(const u32*)(pl + 8);
        }
#pragma unroll
        for (int mi = 0; mi < 2; mi++)
#pragma unroll
            for (int ni = 0; ni < 2; ni++) {
                mma_bf16(c[mi][ni], ah[mi][0], ah[mi][1], ah[mi][2], ah[mi][3],
                         bh[ni][0], bh[ni][1]);
                mma_bf16(c[mi][ni], al[mi][0], al[mi][1], al[mi][2], al[mi][3],
                         bh[ni][0], bh[ni][1]);
                mma_bf16(c[mi][ni], ah[mi][0], ah[mi][1], ah[mi][2], ah[mi][3],
                         bl[ni][0], bl[ni][1]);
            }
    }

    // epilogue: read S(fp16), add, mask, exp, round to fp16, store P, sum
    float rs[2][2] = {};
#pragma unroll
    for (int mi = 0; mi < 2; mi++) {
        const int b0  = mi * 16 + g;
        const int b1  = b0 + 8;
        const int vl0 = vls[b0];
        const int vl1 = vls[b1];
#pragma unroll
        for (int ni = 0; ni < 2; ni++) {
            const int col = kt + wn + ni * 8 + 2 * tg;
            {
                float2 s0 = __half22float2(
                    *(const __half2*)&g_S[((size_t)b0 * TQ_ + q) * TK_ + col]);
                float e0 = (col     < vl0) ? __expf((s0.x + c[mi][ni][0]) * 0.125f) : 0.f;
                float e1 = (col + 1 < vl0) ? __expf((s0.y + c[mi][ni][1]) * 0.125f) : 0.f;
                __half2 hp = __floats2half2_rn(e0, e1);
                *(__half2*)&g_P[((size_t)b0 * TQ_ + q) * TK_ + col] = hp;
                float2 er = __half22float2(hp);
                rs[mi][0] += er.x + er.y;
            }
            {
                float2 s1 = __half22float2(
                    *(const __half2*)&g_S[((size_t)b1 * TQ_ + q) * TK_ + col]);
                float e0 = (col     < vl1) ? __expf((s1.x + c[mi][ni][2]) * 0.125f) : 0.f;
                float e1 = (col + 1 < vl1) ? __expf((s1.y + c[mi][ni][3]) * 0.125f) : 0.f;
                __half2 hp = __floats2half2_rn(e0, e1);
                *(__half2*)&g_P[((size_t)b1 * TQ_ + q) * TK_ + col] = hp;
                float2 er = __half22float2(hp);
                rs[mi][1] += er.x + er.y;
            }
        }
    }
#pragma unroll
    for (int mi = 0; mi < 2; mi++)
#pragma unroll
        for (int r = 0; r < 2; r++) {
            rs[mi][r] += __shfl_xor_sync(0xffffffffu, rs[mi][r], 1);
            rs[mi][r] += __shfl_xor_sync(0xffffffffu, rs[mi][r], 2);
        }
    if (tg == 0) {
#pragma unroll
        for (int mi = 0; mi < 2; mi++) {
            rsum[mi * 16 + g][wid]     = rs[mi][0];
            rsum[mi * 16 + g + 8][wid] = rs[mi][1];
        }
    }
    __syncthreads();
    if (tid < 32) {
        float4 a = *(float4*)&rsum[tid][0];
        float4 b = *(float4*)&rsum[tid][4];
        g_psum[((size_t)tid * TQ_ + q) * 8 + blockIdx.x] =
            ((a.x + a.y) + (a.z + a.w)) + ((b.x + b.y) + (b.z + b.w));
    }
}

// ---------------------------------------------------------------------------
// Kernel C: O = (1/sum) * P(fp16) · V. grid (16,32). f16 MMA.
// 3-stage cp.async pipeline, one barrier per chunk; dynamic smem.
// ---------------------------------------------------------------------------
#define PV_AH_BYTES (3 * 64 * STRD * 2)
#define PV_VS_BYTES (3 * 64 * VSTR * 4)
#define PV_SMEM     (PV_AH_BYTES + PV_VS_BYTES + 64 * 4)

extern "C" __global__ void __launch_bounds__(256)
pv_kernel(const float* __restrict__ V, float* __restrict__ Out)
{
    extern __shared__ char dynbuf[];
    __half* AhB  = (__half*)dynbuf;                       // [3][64][STRD]
    float*  VsB  = (float*)(dynbuf + PV_AH_BYTES);        // [3][64][VSTR]
    float*  invs = (float*)(dynbuf + PV_AH_BYTES + PV_VS_BYTES);

    const int bz = blockIdx.y;
    const int qt = blockIdx.x * 64;
    const float* Vb = V + (size_t)bz * TK_ * D_;
    const __half* Pb = g_P + (size_t)bz * TQ_ * TK_;

    const int tid = threadIdx.x;
    if (tid < 64) {
        const float* ps = &g_psum[((size_t)bz * TQ_ + qt + tid) * 8];
        float4 a = *(const float4*)ps;
        float4 b = *(const float4*)(ps + 4);
        invs[tid] = 1.0f / (((a.x + a.y) + (a.z + a.w)) + ((b.x + b.y) + (b.z + b.w)));
    }

    auto load_stage = [&](int s, int kt) {
        __half* A = AhB + s * 64 * STRD;
        float*  Vt = VsB + s * 64 * VSTR;
#pragma unroll
        for (int i = 0; i < 2; i++) {          // P: 512 x 16B
            int idx = tid + i * 256;
            int r  = idx >> 3;
            int kc = (idx & 7) * 8;
            cp16(A + r * STRD + kc, Pb + (size_t)(qt + r) * TK_ + kt + kc);
        }
#pragma unroll
        for (int i = 0; i < 4; i++) {          // V: 1024 x 16B
            int idx = tid + i * 256;
            int k  = idx >> 4;
            int dc = (idx & 15) * 4;
            cp16(Vt + k * VSTR + dc, Vb + (size_t)(kt + k) * D_ + dc);
        }
        CP_COMMIT();
    };

    const int wid = tid >> 5, lane = tid & 31;
    const int g = lane >> 2, tg = lane & 3;
    const int wm = (wid >> 2) * 32;
    const int wn = (wid & 3) * 16;

    float c[2][2][4] = {};

    load_stage(0, 0);
    load_stage(1, 64);
    for (int ci = 0; ci < 16; ci++) {
        if (ci == 15) { CP_WAIT0(); } else { CP_WAIT1(); }
        __syncthreads();
        if (ci + 2 < 16) load_stage((ci + 2) % 3, (ci + 2) * 64);

        const int s = ci % 3;
        const __half* A = AhB + s * 64 * STRD;
        const float*  Vt = VsB + s * 64 * VSTR;
#pragma unroll
        for (int k0 = 0; k0 < 64; k0 += 16) {
            u32 a[2][4], bh[2][2], bl[2][2];
#pragma unroll
            for (int mi = 0; mi < 2; mi++) {
                const __half* ph = A + (wm + mi * 16 + g) * STRD + k0 + 2 * tg;
                a[mi][0] = *(const u32*)(ph);
                a[mi][1] = *(const u32*)(ph + 8 * STRD);
                a[mi][2] = *(const u32*)(ph + 8);
                a[mi][3] = *(const u32*)(ph + 8 * STRD + 8);
            }
#pragma unroll
            for (int ni = 0; ni < 2; ni++) {
                const int n = wn + ni * 8 + g;
                const int kb = k0 + 2 * tg;
                split2h(Vt[kb * VSTR + n],       Vt[(kb + 1) * VSTR + n], bh[ni][0], bl[ni][0]);
                split2h(Vt[(kb + 8) * VSTR + n], Vt[(kb + 9) * VSTR + n], bh[ni][1], bl[ni][1]);
            }
#pragma unroll
            for (int mi = 0; mi < 2; mi++)
#pragma unroll
                for (int ni = 0; ni < 2; ni++) {
                    mma_f16(c[mi][ni], a[mi][0], a[mi][1], a[mi][2], a[mi][3],
                            bh[ni][0], bh[ni][1]);
                    mma_f16(c[mi][ni], a[mi][0], a[mi][1], a[mi][2], a[mi][3],
                            bl[ni][0], bl[ni][1]);
                }
        }
    }

#pragma unroll
    for (int mi = 0; mi < 2; mi++)
#pragma unroll
        for (int ni = 0; ni < 2; ni++) {
            int m = wm + mi * 16 + g;
            int n = wn + ni * 8 + 2 * tg;
            float inv0 = invs[m], inv1 = invs[m + 8];
            float* d0 = Out + ((size_t)bz * TQ_ + qt + m) * D_ + n;
            *(float2*)d0 = make_float2(c[mi][ni][0] * inv0, c[mi][ni][1] * inv0);
            float* d1 = Out + ((size_t)bz * TQ_ + qt + m + 8) * D_ + n;
            *(float2*)d1 = make_float2(c[mi][ni][2] * inv1, c[mi][ni][3] * inv1);
        }
}

// ---------------------------------------------------------------------------
// Kernel D: O += (1/sum) * P(fp16) · pos_v[q]. grid (1024). f16 MMA.
// 3-stage cp.async pipeline, one barrier per chunk; dynamic smem.
// ---------------------------------------------------------------------------
#define POSV_AH_BYTES (3 * 32 * STRD * 2)
#define POSV_VS_BYTES (3 * 64 * VSTR * 4)
#define POSV_SMEM     (POSV_AH_BYTES + POSV_VS_BYTES + B_ * 4)

extern "C" __global__ void __launch_bounds__(256)
posv_kernel(const float* __restrict__ PV, float* __restrict__ Out)
{
    extern __shared__ char dynbuf[];
    __half* AhB  = (__half*)dynbuf;                        // [3][32][STRD]
    float*  PVsB = (float*)(dynbuf + POSV_AH_BYTES);       // [3][64][VSTR]
    float*  invs = (float*)(dynbuf + POSV_AH_BYTES + POSV_VS_BYTES);

    const int q = blockIdx.x;
    const int tid = threadIdx.x;
    if (tid < B_) {
        const float* ps = &g_psum[((size_t)tid * TQ_ + q) * 8];
        float4 a = *(const float4*)ps;
        float4 b = *(const float4*)(ps + 4);
        invs[tid] = 1.0f / (((a.x + a.y) + (a.z + a.w)) + ((b.x + b.y) + (b.z + b.w)));
    }

    auto load_stage = [&](int s, int kt) {
        __half* A = AhB + s * 32 * STRD;
        float*  Vt = PVsB + s * 64 * VSTR;
        {                                       // P: 256 x 16B
            int bb = tid >> 3;
            int kc = (tid & 7) * 8;
            cp16(A + bb * STRD + kc, g_P + ((size_t)bb * TQ_ + q) * TK_ + kt + kc);
        }
        const float* PVq = PV + ((size_t)q * TK_ + kt) * D_;
#pragma unroll
        for (int i = 0; i < 4; i++) {           // pos_v: 1024 x 16B
            int idx = tid + i * 256;
            int k  = idx >> 4;
            int dc = (idx & 15) * 4;
            cp16(Vt + k * VSTR + dc, PVq + (size_t)k * D_ + dc);
        }
        CP_COMMIT();
    };

    const int wid = tid >> 5, lane = tid & 31;
    const int g = lane >> 2, tg = lane & 3;
    const int wn = wid * 8;

    float c[2][4] = {};

    load_stage(0, 0);
    load_stage(1, 64);
    for (int ci = 0; ci < 16; ci++) {
        if (ci == 15) { CP_WAIT0(); } else { CP_WAIT1(); }
        __syncthreads();
        if (ci + 2 < 16) load_stage((ci + 2) % 3, (ci + 2) * 64);

        const int s = ci % 3;
        const __half* A = AhB + s * 32 * STRD;
        const float*  Vt = PVsB + s * 64 * VSTR;
#pragma unroll
        for (int k0 = 0; k0 < 64; k0 += 16) {
            u32 a[2][4], bh[2], bl[2];
#pragma unroll
            for (int mi = 0; mi < 2; mi++) {
                const __half* ph = A + (mi * 16 + g) * STRD + k0 + 2 * tg;
                a[mi][0] = *(const u32*)(ph);
                a[mi][1] = *(const u32*)(ph + 8 * STRD);
                a[mi][2] = *(const u32*)(ph + 8);
                a[mi][3] = *(const u32*)(ph + 8 * STRD + 8);
            }
            {
                const int n = wn + g;
                const int kb = k0 + 2 * tg;
                split2h(Vt[kb * VSTR + n],       Vt[(kb + 1) * VSTR + n], bh[0], bl[0]);
                split2h(Vt[(kb + 8) * VSTR + n], Vt[(kb + 9) * VSTR + n], bh[1], bl[1]);
            }
#pragma unroll
            for (int mi = 0; mi < 2; mi++) {
                mma_f16(c[mi], a[mi][0], a[mi][1], a[mi][2], a[mi][3], bh[0], bh[1]);
                mma_f16(c[mi], a[mi][0], a[mi][1], a[mi][2], a[mi][3], bl[0], bl[1]);
            }
        }
    }

#pragma unroll
    for (int mi = 0; mi < 2; mi++) {
        const int b0 = mi * 16 + g;
        const int b1 = b0 + 8;
        const int n  = wn + 2 * tg;
        float* d0 = Out + ((size_t)b0 * TQ_ + q) * D_ + n;
        float2 o0 = *(float2*)d0;
        o0.x += c[mi][0] * invs[b0];
        o0.y += c[mi][1] * invs[b0];
        *(float2*)d0 = o0;
        float* d1 = Out + ((size_t)b1 * TQ_ + q) * D_ + n;
        float2 o1 = *(float2*)d1;
        o1.x += c[mi][2] * invs[b1];
        o1.y += c[mi][3] * invs[b1];
        *(float2*)d1 = o1;
    }
}

// ---------------------------------------------------------------------------
extern "C" void kernel_launch(void* const* d_in, const int* in_sizes, int n_in,
                              void* d_out, int out_size)
{
    const float* Q  = (const float*)d_in[0];
    const float* K  = (const float*)d_in[1];
    const float* V  = (const float*)d_in[2];
    const float* PK = (const float*)d_in[3];
    const float* PV = (const float*)d_in[4];
    const int*   VL = (const int*)d_in[5];
    float* Out = (float*)d_out;

    cudaFuncSetAttribute(pv_kernel, cudaFuncAttributeMaxDynamicSharedMemorySize,
                         PV_SMEM);
    cudaFuncSetAttribute(posv_kernel, cudaFuncAttributeMaxDynamicSharedMemorySize,
                         POSV_SMEM);

    qk_kernel<<<dim3(TK_ / 64, TQ_ / 64, B_), 256>>>(Q, K);
    posk_kernel<<<dim3(TK_ / 128, TQ_), 256>>>(Q, PK, VL);
    pv_kernel<<<dim3(TQ_ / 64, B_), 256, PV_SMEM>>>(V, Out);
    posv_kernel<<<TQ_, 256, POSV_SMEM>>>(PV, Out);
}

// round 9
// speedup vs baseline: 4.5116x; 1.0100x over previous
#include <cuda_runtime.h>
#include <cuda_bf16.h>
#include <cuda_fp16.h>
#include <math.h>

typedef unsigned u32;

#define B_  32
#define TQ_ 1024
#define TK_ 1024
#define D_  64
#define STRD 72   // smem row stride in 2B elems (64 data + 8 pad): conflict-free frags
#define VSTR 68   // fp32 V-tile row stride (conflict-free for split reads)

// scratch: fp16 scores/probs, partial rowsums, precomputed bf16 hi/lo Q,K
static __device__ __half g_S[(size_t)B_ * TQ_ * TK_];
static __device__ __half g_P[(size_t)B_ * TQ_ * TK_];
static __device__ float  g_psum[(size_t)B_ * TQ_ * 8];
static __device__ __nv_bfloat16 g_Qh[(size_t)B_ * TQ_ * D_];
static __device__ __nv_bfloat16 g_Ql[(size_t)B_ * TQ_ * D_];
static __device__ __nv_bfloat16 g_Kh[(size_t)B_ * TK_ * D_];
static __device__ __nv_bfloat16 g_Kl[(size_t)B_ * TK_ * D_];

// ---- mma helpers ----------------------------------------------------------
__device__ __forceinline__ void mma_bf16(float c[4], u32 a0, u32 a1, u32 a2, u32 a3,
                                         u32 b0, u32 b1)
{
    asm volatile(
        "mma.sync.aligned.m16n8k16.row.col.f32.bf16.bf16.f32 "
        "{%0,%1,%2,%3},{%4,%5,%6,%7},{%8,%9},{%0,%1,%2,%3};\n"
        : "+f"(c[0]), "+f"(c[1]), "+f"(c[2]), "+f"(c[3])
        : "r"(a0), "r"(a1), "r"(a2), "r"(a3), "r"(b0), "r"(b1));
}
__device__ __forceinline__ void mma_f16(float c[4], u32 a0, u32 a1, u32 a2, u32 a3,
                                        u32 b0, u32 b1)
{
    asm volatile(
        "mma.sync.aligned.m16n8k16.row.col.f32.f16.f16.f32 "
        "{%0,%1,%2,%3},{%4,%5,%6,%7},{%8,%9},{%0,%1,%2,%3};\n"
        : "+f"(c[0]), "+f"(c[1]), "+f"(c[2]), "+f"(c[3])
        : "r"(a0), "r"(a1), "r"(a2), "r"(a3), "r"(b0), "r"(b1));
}

__device__ __forceinline__ u32 cvt2bf(float hi, float lo) {
    u32 r;
    asm("cvt.rn.bf16x2.f32 %0,%1,%2;" : "=r"(r) : "f"(hi), "f"(lo));
    return r;
}
// bf16 hi/lo split (x0 -> low half, x1 -> high half)
__device__ __forceinline__ void split2(float x0, float x1, u32& h, u32& l) {
    h = cvt2bf(x1, x0);
    float h0 = __uint_as_float(h << 16);
    float h1 = __uint_as_float(h & 0xffff0000u);
    l = cvt2bf(x1 - h1, x0 - h0);
}
// fp16 hi/lo split
__device__ __forceinline__ void split2h(float x0, float x1, u32& h, u32& l) {
    __half2 hh = __floats2half2_rn(x0, x1);
    h = *(u32*)&hh;
    float2 hf = __half22float2(hh);
    __half2 ll = __floats2half2_rn(x0 - hf.x, x1 - hf.y);
    l = *(u32*)&ll;
}

// ---- cp.async helpers -----------------------------------------------------
__device__ __forceinline__ void cp16(void* dst_smem, const void* src) {
    u32 d = (u32)__cvta_generic_to_shared(dst_smem);
    asm volatile("cp.async.cg.shared.global [%0], [%1], 16;\n" :: "r"(d), "l"(src));
}
#define CP_COMMIT() asm volatile("cp.async.commit_group;\n" ::)
#define CP_WAIT1()  asm volatile("cp.async.wait_group 1;\n" ::)
#define CP_WAIT0()  asm volatile("cp.async.wait_group 0;\n" ::)

// ---------------------------------------------------------------------------
// Kernel P0: precompute bf16 hi/lo for Q and K (row-major, same layout)
// grid 2048, block 256: one float4 of Q and K per thread.
// ---------------------------------------------------------------------------
extern "C" __global__ void __launch_bounds__(256)
prep_qk_kernel(const float* __restrict__ Q, const float* __restrict__ K)
{
    size_t idx = (size_t)blockIdx.x * 256 + threadIdx.x;
    float4 v = ((const float4*)Q)[idx];
    u32 h0, l0, h1, l1;
    split2(v.x, v.y, h0, l0); split2(v.z, v.w, h1, l1);
    ((uint2*)g_Qh)[idx] = make_uint2(h0, h1);
    ((uint2*)g_Ql)[idx] = make_uint2(l0, l1);
    float4 w = ((const float4*)K)[idx];
    split2(w.x, w.y, h0, l0); split2(w.z, w.w, h1, l1);
    ((uint2*)g_Kh)[idx] = make_uint2(h0, h1);
    ((uint2*)g_Kl)[idx] = make_uint2(l0, l1);
}

// ---------------------------------------------------------------------------
// Kernel A: S[b,q,k] = Q[b,q,:]·K[b,k,:] (unscaled, fp16 out). bf16x3 MMA.
// Operand tiles loaded via cp.async from precomputed hi/lo arrays.
// ---------------------------------------------------------------------------
extern "C" __global__ void __launch_bounds__(256)
qk_kernel()
{
    const int bz = blockIdx.z;
    const int qt = blockIdx.y * 64;
    const int kt = blockIdx.x * 64;
    __half* Sb = g_S + (size_t)bz * TQ_ * TK_;

    __shared__ __nv_bfloat16 Ah[64][STRD], Al[64][STRD];
    __shared__ __nv_bfloat16 Bh[64][STRD], Bl[64][STRD];

    const int tid = threadIdx.x;
    {
        const __nv_bfloat16* qh = g_Qh + ((size_t)bz * TQ_ + qt) * D_;
        const __nv_bfloat16* ql = g_Ql + ((size_t)bz * TQ_ + qt) * D_;
        const __nv_bfloat16* kh = g_Kh + ((size_t)bz * TK_ + kt) * D_;
        const __nv_bfloat16* kl = g_Kl + ((size_t)bz * TK_ + kt) * D_;
#pragma unroll
        for (int i = 0; i < 2; i++) {
            int idx = tid + i * 256;         // 512 chunks over 64 rows x 8
            int row = idx >> 3;
            int c8  = (idx & 7) * 8;
            cp16(&Ah[row][c8], qh + row * D_ + c8);
            cp16(&Al[row][c8], ql + row * D_ + c8);
            cp16(&Bh[row][c8], kh + row * D_ + c8);
            cp16(&Bl[row][c8], kl + row * D_ + c8);
        }
    }
    CP_COMMIT();
    CP_WAIT0();
    __syncthreads();

    const int wid = tid >> 5, lane = tid & 31;
    const int g = lane >> 2, tg = lane & 3;
    const int wm = (wid >> 2) * 32;
    const int wn = (wid & 3) * 16;

    float c[2][2][4] = {};

#pragma unroll
    for (int k0 = 0; k0 < 64; k0 += 16) {
        u32 ah[2][4], al[2][4], bh[2][2], bl[2][2];
#pragma unroll
        for (int mi = 0; mi < 2; mi++) {
            const __nv_bfloat16* ph = &Ah[wm + mi * 16 + g][k0 + 2 * tg];
            ah[mi][0] = *(const u32*)(ph);
            ah[mi][1] = *(const u32*)(ph + 8 * STRD);
            ah[mi][2] = *(const u32*)(ph + 8);
            ah[mi][3] = *(const u32*)(ph + 8 * STRD + 8);
            const __nv_bfloat16* pl = &Al[wm + mi * 16 + g][k0 + 2 * tg];
            al[mi][0] = *(const u32*)(pl);
            al[mi][1] = *(const u32*)(pl + 8 * STRD);
            al[mi][2] = *(const u32*)(pl + 8);
            al[mi][3] = *(const u32*)(pl + 8 * STRD + 8);
        }
#pragma unroll
        for (int ni = 0; ni < 2; ni++) {
            const __nv_bfloat16* ph = &Bh[wn + ni * 8 + g][k0 + 2 * tg];
            bh[ni][0] = *(const u32*)(ph);
            bh[ni][1] = *(const u32*)(ph + 8);
            const __nv_bfloat16* pl = &Bl[wn + ni * 8 + g][k0 + 2 * tg];
            bl[ni][0] = *(const u32*)(pl);
            bl[ni][1] = *(const u32*)(pl + 8);
        }
#pragma unroll
        for (int mi = 0; mi < 2; mi++)
#pragma unroll
            for (int ni = 0; ni < 2; ni++) {
                mma_bf16(c[mi][ni], ah[mi][0], ah[mi][1], ah[mi][2], ah[mi][3],
                         bh[ni][0], bh[ni][1]);
                mma_bf16(c[mi][ni], al[mi][0], al[mi][1], al[mi][2], al[mi][3],
                         bh[ni][0], bh[ni][1]);
                mma_bf16(c[mi][ni], ah[mi][0], ah[mi][1], ah[mi][2], ah[mi][3],
                         bl[ni][0], bl[ni][1]);
            }
    }

#pragma unroll
    for (int mi = 0; mi < 2; mi++)
#pragma unroll
        for (int ni = 0; ni < 2; ni++) {
            int m = qt + wm + mi * 16 + g;
            int n = kt + wn + ni * 8 + 2 * tg;
            *(__half2*)&Sb[(size_t)m * TK_ + n] =
                __floats2half2_rn(c[mi][ni][0], c[mi][ni][1]);
            *(__half2*)&Sb[(size_t)(m + 8) * TK_ + n] =
                __floats2half2_rn(c[mi][ni][2], c[mi][ni][3]);
        }
}

// ---------------------------------------------------------------------------
// Kernel B: P(fp16) = exp(mask((S + Q·pos_k)/8)); emits partial rowsums.
// pos_k staged fp32 via cp.async with XOR swizzle; bf16 split on the fly.
// ---------------------------------------------------------------------------
__device__ __forceinline__ int bswz(int n, int c) {
    return n * 64 + ((((c >> 2) ^ (n & 7)) << 2) | (c & 3));
}

extern "C" __global__ void __launch_bounds__(256)
posk_kernel(const float* __restrict__ PK, const int* __restrict__ VL)
{
    const int q  = blockIdx.y;
    const int kt = blockIdx.x * 128;

    __shared__ __nv_bfloat16 Ah[32][STRD], Al[32][STRD];  // Q rows (per b)
    __shared__ float Bs[128 * 64];                        // pos_k fp32, swizzled
    __shared__ float rsum[32][8];
    __shared__ int vls[B_];

    const int tid = threadIdx.x;
    {
        // Q rows: b = row, source g_Qh/[b][q][*]; 256 chunks, 1 per thread
        int row = tid >> 3;
        int c8  = (tid & 7) * 8;
        cp16(&Ah[row][c8], g_Qh + ((size_t)row * TQ_ + q) * D_ + c8);
        cp16(&Al[row][c8], g_Ql + ((size_t)row * TQ_ + q) * D_ + c8);
    }
    {
        const float* PKq = PK + ((size_t)q * TK_ + kt) * D_;
#pragma unroll
        for (int i = 0; i < 8; i++) {        // 2048 16B chunks over 128x64
            int idx = tid + i * 256;
            int row = idx >> 4;
            int c4  = idx & 15;
            cp16(&Bs[row * 64 + ((c4 ^ (row & 7)) << 2)], PKq + row * 64 + c4 * 4);
        }
    }
    CP_COMMIT();
    if (tid < B_) vls[tid] = VL[tid];
    CP_WAIT0();
    __syncthreads();

    const int wid = tid >> 5, lane = tid & 31;
    const int g = lane >> 2, tg = lane & 3;
    const int wn = wid * 16;

    float c[2][2][4] = {};

#pragma unroll
    for (int k0 = 0; k0 < 64; k0 += 16) {
        u32 ah[2][4], al[2][4], bh[2][2], bl[2][2];
#pragma unroll
        for (int mi = 0; mi < 2; mi++) {
            const __nv_bfloat16* ph = &Ah[mi * 16 + g][k0 + 2 * tg];
            ah[mi][0] = *(const u32*)(ph);
            ah[mi][1] = *(const u32*)(ph + 8 * STRD);
            ah[mi][2] = *(const u32*)(ph + 8);
            ah[mi][3] = *(const u32*)(ph + 8 * STRD + 8);
            const __nv_bfloat16* pl = &Al[mi * 16 + g][k0 + 2 * tg];
            al[mi][0] = *(const u32*)(pl);
            al[mi][1] = *(const u32*)(pl + 8 * STRD);
            al[mi][2] = *(const u32*)(pl + 8);
            al[mi][3] = *(const u32*)(pl + 8 * STRD + 8);
        }
#pragma unroll
        for (int ni = 0; ni < 2; ni++) {
            const int n = wn + ni * 8 + g;
            float2 v0 = *(const float2*)&Bs[bswz(n, k0 + 2 * tg)];
            split2(v0.x, v0.y, bh[ni][0], bl[ni][0]);
            float2 v1 = *(const float2*)&Bs[bswz(n, k0 + 2 * tg + 8)];
            split2(v1.x, v1.y, bh[ni][1], bl[ni][1]);
        }
#pragma unroll
        for (int mi = 0; mi < 2; mi++)
#pragma unroll
            for (int ni = 0; ni < 2; ni++) {
                mma_bf16(c[mi][ni], ah[mi][0], ah[mi][1], ah[mi][2], ah[mi][3],
                         bh[ni][0], bh[ni][1]);
                mma_bf16(c[mi][ni], al[mi][0], al[mi][1], al[mi][2], al[mi][3],
                         bh[ni][0], bh[ni][1]);
                mma_bf16(c[mi][ni], ah[mi][0], ah[mi][1], ah[mi][2], ah[mi][3],
                         bl[ni][0], bl[ni][1]);
            }
    }

    // epilogue: read S(fp16), add, mask, exp, round to fp16, store P, sum
    float rs[2][2] = {};
#pragma unroll
    for (int mi = 0; mi < 2; mi++) {
        const int b0  = mi * 16 + g;
        const int b1  = b0 + 8;
        const int vl0 = vls[b0];
        const int vl1 = vls[b1];
#pragma unroll
        for (int ni = 0; ni < 2; ni++) {
            const int col = kt + wn + ni * 8 + 2 * tg;
            {
                float2 s0 = __half22float2(
                    *(const __half2*)&g_S[((size_t)b0 * TQ_ + q) * TK_ + col]);
                float e0 = (col     < vl0) ? __expf((s0.x + c[mi][ni][0]) * 0.125f) : 0.f;
                float e1 = (col + 1 < vl0) ? __expf((s0.y + c[mi][ni][1]) * 0.125f) : 0.f;
                __half2 hp = __floats2half2_rn(e0, e1);
                *(__half2*)&g_P[((size_t)b0 * TQ_ + q) * TK_ + col] = hp;
                float2 er = __half22float2(hp);
                rs[mi][0] += er.x + er.y;
            }
            {
                float2 s1 = __half22float2(
                    *(const __half2*)&g_S[((size_t)b1 * TQ_ + q) * TK_ + col]);
                float e0 = (col     < vl1) ? __expf((s1.x + c[mi][ni][2]) * 0.125f) : 0.f;
                float e1 = (col + 1 < vl1) ? __expf((s1.y + c[mi][ni][3]) * 0.125f) : 0.f;
                __half2 hp = __floats2half2_rn(e0, e1);
                *(__half2*)&g_P[((size_t)b1 * TQ_ + q) * TK_ + col] = hp;
                float2 er = __half22float2(hp);
                rs[mi][1] += er.x + er.y;
            }
        }
    }
#pragma unroll
    for (int mi = 0; mi < 2; mi++)
#pragma unroll
        for (int r = 0; r < 2; r++) {
            rs[mi][r] += __shfl_xor_sync(0xffffffffu, rs[mi][r], 1);
            rs[mi][r] += __shfl_xor_sync(0xffffffffu, rs[mi][r], 2);
        }
    if (tg == 0) {
#pragma unroll
        for (int mi = 0; mi < 2; mi++) {
            rsum[mi * 16 + g][wid]     = rs[mi][0];
            rsum[mi * 16 + g + 8][wid] = rs[mi][1];
        }
    }
    __syncthreads();
    if (tid < 32) {
        float4 a = *(float4*)&rsum[tid][0];
        float4 b = *(float4*)&rsum[tid][4];
        g_psum[((size_t)tid * TQ_ + q) * 8 + blockIdx.x] =
            ((a.x + a.y) + (a.z + a.w)) + ((b.x + b.y) + (b.z + b.w));
    }
}

// ---------------------------------------------------------------------------
// Kernel C: O = (1/sum) * P(fp16) · V. grid (16,32). f16 MMA.
// 3-stage cp.async pipeline, one barrier per chunk; dynamic smem.
// ---------------------------------------------------------------------------
#define PV_AH_BYTES (3 * 64 * STRD * 2)
#define PV_VS_BYTES (3 * 64 * VSTR * 4)
#define PV_SMEM     (PV_AH_BYTES + PV_VS_BYTES + 64 * 4)

extern "C" __global__ void __launch_bounds__(256)
pv_kernel(const float* __restrict__ V, float* __restrict__ Out)
{
    extern __shared__ char dynbuf[];
    __half* AhB  = (__half*)dynbuf;                       // [3][64][STRD]
    float*  VsB  = (float*)(dynbuf + PV_AH_BYTES);        // [3][64][VSTR]
    float*  invs = (float*)(dynbuf + PV_AH_BYTES + PV_VS_BYTES);

    const int bz = blockIdx.y;
    const int qt = blockIdx.x * 64;
    const float* Vb = V + (size_t)bz * TK_ * D_;
    const __half* Pb = g_P + (size_t)bz * TQ_ * TK_;

    const int tid = threadIdx.x;
    if (tid < 64) {
        const float* ps = &g_psum[((size_t)bz * TQ_ + qt + tid) * 8];
        float4 a = *(const float4*)ps;
        float4 b = *(const float4*)(ps + 4);
        invs[tid] = 1.0f / (((a.x + a.y) + (a.z + a.w)) + ((b.x + b.y) + (b.z + b.w)));
    }

    auto load_stage = [&](int s, int kt) {
        __half* A = AhB + s * 64 * STRD;
        float*  Vt = VsB + s * 64 * VSTR;
#pragma unroll
        for (int i = 0; i < 2; i++) {          // P: 512 x 16B
            int idx = tid + i * 256;
            int r  = idx >> 3;
            int kc = (idx & 7) * 8;
            cp16(A + r * STRD + kc, Pb + (size_t)(qt + r) * TK_ + kt + kc);
        }
#pragma unroll
        for (int i = 0; i < 4; i++) {          // V: 1024 x 16B
            int idx = tid + i * 256;
            int k  = idx >> 4;
            int dc = (idx & 15) * 4;
            cp16(Vt + k * VSTR + dc, Vb + (size_t)(kt + k) * D_ + dc);
        }
        CP_COMMIT();
    };

    const int wid = tid >> 5, lane = tid & 31;
    const int g = lane >> 2, tg = lane & 3;
    const int wm = (wid >> 2) * 32;
    const int wn = (wid & 3) * 16;

    float c[2][2][4] = {};

    load_stage(0, 0);
    load_stage(1, 64);
    for (int ci = 0; ci < 16; ci++) {
        if (ci == 15) { CP_WAIT0(); } else { CP_WAIT1(); }
        __syncthreads();
        if (ci + 2 < 16) load_stage((ci + 2) % 3, (ci + 2) * 64);

        const int s = ci % 3;
        const __half* A = AhB + s * 64 * STRD;
        const float*  Vt = VsB + s * 64 * VSTR;
#pragma unroll
        for (int k0 = 0; k0 < 64; k0 += 16) {
            u32 a[2][4], bh[2][2], bl[2][2];
#pragma unroll
            for (int mi = 0; mi < 2; mi++) {
                const __half* ph = A + (wm + mi * 16 + g) * STRD + k0 + 2 * tg;
                a[mi][0] = *(const u32*)(ph);
                a[mi][1] = *(const u32*)(ph + 8 * STRD);
                a[mi][2] = *(const u32*)(ph + 8);
                a[mi][3] = *(const u32*)(ph + 8 * STRD + 8);
            }
#pragma unroll
            for (int ni = 0; ni < 2; ni++) {
                const int n = wn + ni * 8 + g;
                const int kb = k0 + 2 * tg;
                split2h(Vt[kb * VSTR + n],       Vt[(kb + 1) * VSTR + n], bh[ni][0], bl[ni][0]);
                split2h(Vt[(kb + 8) * VSTR + n], Vt[(kb + 9) * VSTR + n], bh[ni][1], bl[ni][1]);
            }
#pragma unroll
            for (int mi = 0; mi < 2; mi++)
#pragma unroll
                for (int ni = 0; ni < 2; ni++) {
                    mma_f16(c[mi][ni], a[mi][0], a[mi][1], a[mi][2], a[mi][3],
                            bh[ni][0], bh[ni][1]);
                    mma_f16(c[mi][ni], a[mi][0], a[mi][1], a[mi][2], a[mi][3],
                            bl[ni][0], bl[ni][1]);
                }
        }
    }

#pragma unroll
    for (int mi = 0; mi < 2; mi++)
#pragma unroll
        for (int ni = 0; ni < 2; ni++) {
            int m = wm + mi * 16 + g;
            int n = wn + ni * 8 + 2 * tg;
            float inv0 = invs[m], inv1 = invs[m + 8];
            float* d0 = Out + ((size_t)bz * TQ_ + qt + m) * D_ + n;
            *(float2*)d0 = make_float2(c[mi][ni][0] * inv0, c[mi][ni][1] * inv0);
            float* d1 = Out + ((size_t)bz * TQ_ + qt + m + 8) * D_ + n;
            *(float2*)d1 = make_float2(c[mi][ni][2] * inv1, c[mi][ni][3] * inv1);
        }
}

// ---------------------------------------------------------------------------
// Kernel D: O += (1/sum) * P(fp16) · pos_v[q]. grid (1024). f16 MMA.
// 2-stage cp.async pipeline (measured best); static smem.
// ---------------------------------------------------------------------------
extern "C" __global__ void __launch_bounds__(256)
posv_kernel(const float* __restrict__ PV, float* __restrict__ Out)
{
    const int q = blockIdx.x;

    __shared__ __half Ahs[2][32][STRD];   // P chunks fp16
    __shared__ float  PVs[2][64][VSTR];   // pos_v chunks fp32 [k][d]
    __shared__ float  invs[B_];

    const int tid = threadIdx.x;
    if (tid < B_) {
        const float* ps = &g_psum[((size_t)tid * TQ_ + q) * 8];
        float4 a = *(const float4*)ps;
        float4 b = *(const float4*)(ps + 4);
        invs[tid] = 1.0f / (((a.x + a.y) + (a.z + a.w)) + ((b.x + b.y) + (b.z + b.w)));
    }

    auto load_stage = [&](int s, int kt) {
        {                                       // P: 256 x 16B
            int bb = tid >> 3;
            int kc = (tid & 7) * 8;
            cp16(&Ahs[s][bb][kc], g_P + ((size_t)bb * TQ_ + q) * TK_ + kt + kc);
        }
        const float* PVq = PV + ((size_t)q * TK_ + kt) * D_;
#pragma unroll
        for (int i = 0; i < 4; i++) {           // pos_v: 1024 x 16B
            int idx = tid + i * 256;
            int k  = idx >> 4;
            int dc = (idx & 15) * 4;
            cp16(&PVs[s][k][dc], PVq + (size_t)k * D_ + dc);
        }
        CP_COMMIT();
    };

    const int wid = tid >> 5, lane = tid & 31;
    const int g = lane >> 2, tg = lane & 3;
    const int wn = wid * 8;

    float c[2][4] = {};

    load_stage(0, 0);
    for (int ci = 0; ci < 16; ci++) {
        const int s = ci & 1;
        if (ci < 15) { load_stage(s ^ 1, (ci + 1) * 64); CP_WAIT1(); }
        else         { CP_WAIT0(); }
        __syncthreads();

#pragma unroll
        for (int k0 = 0; k0 < 64; k0 += 16) {
            u32 a[2][4], bh[2], bl[2];
#pragma unroll
            for (int mi = 0; mi < 2; mi++) {
                const __half* ph = &Ahs[s][mi * 16 + g][k0 + 2 * tg];
                a[mi][0] = *(const u32*)(ph);
                a[mi][1] = *(const u32*)(ph + 8 * STRD);
                a[mi][2] = *(const u32*)(ph + 8);
                a[mi][3] = *(const u32*)(ph + 8 * STRD + 8);
            }
            {
                const int n = wn + g;
                const int kb = k0 + 2 * tg;
                split2h(PVs[s][kb][n],     PVs[s][kb + 1][n], bh[0], bl[0]);
                split2h(PVs[s][kb + 8][n], PVs[s][kb + 9][n], bh[1], bl[1]);
            }
#pragma unroll
            for (int mi = 0; mi < 2; mi++) {
                mma_f16(c[mi], a[mi][0], a[mi][1], a[mi][2], a[mi][3], bh[0], bh[1]);
                mma_f16(c[mi], a[mi][0], a[mi][1], a[mi][2], a[mi][3], bl[0], bl[1]);
            }
        }
        __syncthreads();
    }

#pragma unroll
    for (int mi = 0; mi < 2; mi++) {
        const int b0 = mi * 16 + g;
        const int b1 = b0 + 8;
        const int n  = wn + 2 * tg;
        float* d0 = Out + ((size_t)b0 * TQ_ + q) * D_ + n;
        float2 o0 = *(float2*)d0;
        o0.x += c[mi][0] * invs[b0];
        o0.y += c[mi][1] * invs[b0];
        *(float2*)d0 = o0;
        float* d1 = Out + ((size_t)b1 * TQ_ + q) * D_ + n;
        float2 o1 = *(float2*)d1;
        o1.x += c[mi][2] * invs[b1];
        o1.y += c[mi][3] * invs[b1];
        *(float2*)d1 = o1;
    }
}

// ---------------------------------------------------------------------------
extern "C" void kernel_launch(void* const* d_in, const int* in_sizes, int n_in,
                              void* d_out, int out_size)
{
    const float* Q  = (const float*)d_in[0];
    const float* K  = (const float*)d_in[1];
    const float* V  = (const float*)d_in[2];
    const float* PK = (const float*)d_in[3];
    const float* PV = (const float*)d_in[4];
    const int*   VL = (const int*)d_in[5];
    float* Out = (float*)d_out;

    cudaFuncSetAttribute(pv_kernel, cudaFuncAttributeMaxDynamicSharedMemorySize,
                         PV_SMEM);

    prep_qk_kernel<<<2048, 256>>>(Q, K);
    qk_kernel<<<dim3(TK_ / 64, TQ_ / 64, B_), 256>>>();
    posk_kernel<<<dim3(TK_ / 128, TQ_), 256>>>(PK, VL);
    pv_kernel<<<dim3(TQ_ / 64, B_), 256, PV_SMEM>>>(V, Out);
    posv_kernel<<<TQ_, 256>>>(PV, Out);
}